// round 9
// baseline (speedup 1.0000x reference)
#include <cuda_runtime.h>
#include <cuda_fp16.h>
#include <math.h>
#include <stdint.h>

#define B_  4
#define NQ  512
#define NC  2048
#define DQ  1024
#define DC  768
#define CC  1024
#define HH  16
#define HD  64
#define LL  2
#define FF  4096
#define EPSLN 1e-5f

// ---------------- scratch ----------------
__device__ float  g_bufQ [B_*NQ*CC];        // residual stream S0 (fp32)
__device__ float  g_bufQ2[B_*NQ*CC];        // residual stream S1 (fp32)
__device__ float  g_part [2*B_*NQ*CC];      // split-K partials (2 slices)
__device__ __half g_bufC [B_*NC*CC];
__device__ __half g_bufQN[B_*NQ*CC];
__device__ __half g_bufQH[B_*NQ*CC];
__device__ __half g_bufKV[B_*NC*2*CC];
__device__ __half g_bufO [B_*NQ*CC];
__device__ __half g_bufF [B_*NQ*FF];
__device__ __half g_rQuery[B_*NQ*DQ];
__device__ __half g_rCtx  [B_*NC*DC];
__device__ __half g_rWqp  [DQ*CC];
__device__ __half g_rWcp  [DC*CC];
__device__ __half g_rWq   [LL*CC*CC];
__device__ __half g_rWkv  [LL*CC*2*CC];
__device__ __half g_rWo   [LL*CC*CC];
__device__ __half g_rW1   [LL*CC*FF];
__device__ __half g_rW2   [LL*FF*CC];

#define PARTSTRIDE ((size_t)B_*NQ*CC)

#define MMA_F16(D, a0,a1,a2,a3, b0,b1)                                           \
    asm volatile(                                                                \
        "mma.sync.aligned.m16n8k16.row.col.f32.f16.f16.f32 "                     \
        "{%0,%1,%2,%3}, {%4,%5,%6,%7}, {%8,%9}, {%0,%1,%2,%3};\n"                \
        : "+f"((D)[0]), "+f"((D)[1]), "+f"((D)[2]), "+f"((D)[3])                 \
        : "r"(a0), "r"(a1), "r"(a2), "r"(a3), "r"(b0), "r"(b1))

__device__ __forceinline__ void cp16(unsigned dst, const void* src) {
    asm volatile("cp.async.cg.shared.global [%0], [%1], 16;" :: "r"(dst), "l"(src));
}
__device__ __forceinline__ void cpcommit() { asm volatile("cp.async.commit_group;"); }
__device__ __forceinline__ void cpwait0()  { asm volatile("cp.async.wait_group 0;"); }
__device__ __forceinline__ void cpwait1()  { asm volatile("cp.async.wait_group 1;"); }
__device__ __forceinline__ void cpwait2()  { asm volatile("cp.async.wait_group 2;"); }

// ---------------- prep ----------------
__global__ __launch_bounds__(256) void tohalf(
    const float* __restrict__ src, __half* __restrict__ dst, int n)
{
    int i = (blockIdx.x * 256 + threadIdx.x) * 4;
    if (i < n) {
        float4 v = *(const float4*)(src + i);
        __half2* d = (__half2*)(dst + i);
        d[0] = __floats2half2_rn(v.x, v.y);
        d[1] = __floats2half2_rn(v.z, v.w);
    }
}

#define MAXTT 10
struct TTp { const float* s; __half* d; int K; int N; int blk0; };
struct TTtab { TTp p[MAXTT]; };

__global__ void transpose_mega(TTtab tab)
{
    __shared__ float t[32][33];
    int b = blockIdx.x;
    int i = 0;
    #pragma unroll
    for (int j = 1; j < MAXTT; j++)
        if (b >= tab.p[j].blk0) i = j;
    const TTp P = tab.p[i];
    int lid = b - P.blk0;
    int nb  = P.N >> 5;
    const int n0 = (lid % nb) * 32, k0 = (lid / nb) * 32;
    const int tx = threadIdx.x, ty = threadIdx.y;
    #pragma unroll
    for (int q = 0; q < 4; q++)
        t[ty + 8*q][tx] = P.s[(size_t)(k0 + ty + 8*q) * P.N + n0 + tx];
    __syncthreads();
    #pragma unroll
    for (int q = 0; q < 4; q++)
        P.d[(size_t)(n0 + ty + 8*q) * P.K + k0 + tx] = __float2half(t[tx][ty + 8*q]);
}

// ---------------- fp16 GEMM body ----------------
// flags: 1=gelu, 2=half out, 4=partial mode (fp32 store, NO bias/resid/gelu)
__device__ __forceinline__ void gemm_body(
    int bm, int bn, const __half* __restrict__ A, int lda,
    const __half* __restrict__ Bt, int ldb, int kofs, int Kh,
    const float* __restrict__ bias, const float* __restrict__ resid,
    void* __restrict__ outv, int N, int flags)
{
    extern __shared__ uint32_t smu[];
    const int tid  = threadIdx.x;
    const int lane = tid & 31;
    const int warp = tid >> 5;
    const int wmi  = warp >> 2;
    const int wni  = warp & 3;
    const int lr   = lane >> 2;
    const int lc   = lane & 3;

    const int srow = tid >> 1;
    const int c0s  = (tid & 1) * 2;
    const int sswz = ((srow >> 1) & 3) << 2;
    const unsigned sbase = (unsigned)__cvta_generic_to_shared(smu);
    unsigned adst[2], bdst[2];
    #pragma unroll
    for (int i = 0; i < 2; i++) {
        int c = c0s + i;
        adst[i] = sbase + (srow*16 + ((4*c) ^ sswz)) * 4u;
        bdst[i] = sbase + 8192u + (srow*16 + ((4*c) ^ sswz)) * 4u;
    }
    const __half* aSrc = A  + (size_t)(bm + srow) * lda + kofs + 8*c0s;
    const __half* bSrc = Bt + (size_t)(bn + srow) * ldb + kofs + 8*c0s;

    float acc[4][4][4];
    #pragma unroll
    for (int i = 0; i < 4; i++)
        #pragma unroll
        for (int j = 0; j < 4; j++)
            #pragma unroll
            for (int k = 0; k < 4; k++) acc[i][j][k] = 0.f;

    const int T = Kh >> 5;

    #define STAGE(t) do {                                                        \
        const unsigned boff = ((t) & 3) * 16384u;                                \
        const __half* sa = aSrc + (t) * 32;                                      \
        const __half* sb = bSrc + (t) * 32;                                      \
        cp16(adst[0] + boff, sa);                                                \
        cp16(adst[1] + boff, sa + 8);                                            \
        cp16(bdst[0] + boff, sb);                                                \
        cp16(bdst[1] + boff, sb + 8);                                            \
        cpcommit();                                                              \
    } while (0)

    STAGE(0); STAGE(1); STAGE(2);

    const int fswz = ((lr >> 1) & 3) << 2;
    const int abase0 = (wmi*64 + lr) * 16;
    const int bbase0 = (wni*32 + lr) * 16;

    for (int t = 0; t < T; t++) {
        const int rem = T - 1 - t;
        if (rem >= 2) cpwait2(); else if (rem == 1) cpwait1(); else cpwait0();
        __syncthreads();
        if (t + 3 < T) STAGE(t + 3);

        const uint32_t* as = smu + (t & 3) * 4096;
        const uint32_t* bs = as + 2048;

        #pragma unroll
        for (int t16 = 0; t16 < 2; t16++) {
            const int u0 = (8*t16 + lc) ^ fswz;
            const int u1 = u0 ^ 4;
            uint32_t af[4][4], bf[4][2];
            #pragma unroll
            for (int fm = 0; fm < 4; fm++) {
                const uint32_t* p = as + abase0 + fm*256;
                af[fm][0] = p[u0];
                af[fm][1] = p[128 + u0];
                af[fm][2] = p[u1];
                af[fm][3] = p[128 + u1];
            }
            #pragma unroll
            for (int fn = 0; fn < 4; fn++) {
                const uint32_t* p = bs + bbase0 + fn*128;
                bf[fn][0] = p[u0];
                bf[fn][1] = p[u1];
            }
            #pragma unroll
            for (int fm = 0; fm < 4; fm++)
                #pragma unroll
                for (int fn = 0; fn < 4; fn++)
                    MMA_F16(acc[fm][fn], af[fm][0], af[fm][1], af[fm][2], af[fm][3],
                            bf[fn][0], bf[fn][1]);
        }
    }
    #undef STAGE

    const int do_gelu  = flags & 1;
    const int half_out = flags & 2;
    const int partial  = flags & 4;
    #pragma unroll
    for (int fm = 0; fm < 4; fm++) {
        #pragma unroll
        for (int fn = 0; fn < 4; fn++) {
            int row = bm + wmi*64 + fm*16 + lr;
            int col = bn + wni*32 + fn*8 + 2*lc;

            float v0 = acc[fm][fn][0];
            float v1 = acc[fm][fn][1];
            float v2 = acc[fm][fn][2];
            float v3 = acc[fm][fn][3];
            if (!partial) {
                float2 bv = *(const float2*)(bias + col);
                v0 += bv.x; v1 += bv.y; v2 += bv.x; v3 += bv.y;
                if (do_gelu) {
                    v0 = 0.5f * v0 * (1.f + erff(v0 * 0.70710678118654752f));
                    v1 = 0.5f * v1 * (1.f + erff(v1 * 0.70710678118654752f));
                    v2 = 0.5f * v2 * (1.f + erff(v2 * 0.70710678118654752f));
                    v3 = 0.5f * v3 * (1.f + erff(v3 * 0.70710678118654752f));
                }
                if (resid) {
                    float2 r0 = *(const float2*)(resid + (size_t)row * N + col);
                    float2 r1 = *(const float2*)(resid + (size_t)(row + 8) * N + col);
                    v0 += r0.x; v1 += r0.y; v2 += r1.x; v3 += r1.y;
                }
            }
            if (half_out) {
                __half* o = (__half*)outv;
                *(__half2*)(o + (size_t)row * N + col)       = __floats2half2_rn(v0, v1);
                *(__half2*)(o + (size_t)(row + 8) * N + col) = __floats2half2_rn(v2, v3);
            } else {
                float* o = (float*)outv;
                *(float2*)(o + (size_t)row * N + col)        = make_float2(v0, v1);
                *(float2*)(o + (size_t)(row + 8) * N + col)  = make_float2(v2, v3);
            }
        }
    }
}

// single-problem kernel; grid.z = split-K slices writing disjoint partial buffers
__global__ __launch_bounds__(256, 2) void gemm_f16(
    const __half* __restrict__ A, const __half* __restrict__ Bt,
    const float* __restrict__ bias, const float* __restrict__ resid,
    void* __restrict__ outv, int N, int K, int flags)
{
    const int ns = gridDim.z;
    const int Kh = K / ns;
    void* ov = outv;
    if (flags & 4)
        ov = (float*)outv + (size_t)blockIdx.z * PARTSTRIDE;
    gemm_body(blockIdx.y * 128, blockIdx.x * 128, A, K, Bt, K,
              blockIdx.z * Kh, Kh, bias, resid, ov, N, flags);
}

// dual-problem kernel
struct GProb { const __half* A; const __half* Bt; const float* bias;
               void* out; int N; int K; int gx; int flags; };
__global__ __launch_bounds__(256, 2) void gemm_f16_dual(GProb p0, GProb p1, int nblk0)
{
    int b = blockIdx.x;
    if (b < nblk0) {
        gemm_body((b / p0.gx) * 128, (b % p0.gx) * 128, p0.A, p0.K, p0.Bt, p0.K,
                  0, p0.K, p0.bias, nullptr, p0.out, p0.N, p0.flags);
    } else {
        b -= nblk0;
        gemm_body((b / p1.gx) * 128, (b % p1.gx) * 128, p1.A, p1.K, p1.Bt, p1.K,
                  0, p1.K, p1.bias, nullptr, p1.out, p1.N, p1.flags);
    }
}

// ---------------- LayerNorm (standalone, layer-0 first LN only) ----------------
__global__ __launch_bounds__(256) void ln_kernel(
    const float* __restrict__ x, const float* __restrict__ g,
    const float* __restrict__ b, void* __restrict__ yv, int half_out)
{
    __shared__ float red[256];
    const int row = blockIdx.x;
    const int tid = threadIdx.x;
    const float* xr = x + (size_t)row * CC;

    float v[4];
    float s = 0.f;
    #pragma unroll
    for (int i = 0; i < 4; i++) { v[i] = xr[tid + i*256]; s += v[i]; }
    red[tid] = s; __syncthreads();
    for (int off = 128; off > 0; off >>= 1) {
        if (tid < off) red[tid] += red[tid + off];
        __syncthreads();
    }
    const float mean = red[0] * (1.f / CC);
    __syncthreads();

    float sq = 0.f;
    #pragma unroll
    for (int i = 0; i < 4; i++) { float d = v[i] - mean; sq += d * d; }
    red[tid] = sq; __syncthreads();
    for (int off = 128; off > 0; off >>= 1) {
        if (tid < off) red[tid] += red[tid + off];
        __syncthreads();
    }
    const float rstd = rsqrtf(red[0] * (1.f / CC) + EPSLN);

    #pragma unroll
    for (int i = 0; i < 4; i++) {
        int c = tid + i*256;
        float o = (v[i] - mean) * rstd * g[c] + b[c];
        if (half_out) ((__half*)yv)[(size_t)row * CC + c] = __float2half(o);
        else          ((float*)yv)[(size_t)row * CC + c] = o;
    }
}

// ---------------- fused split-K reduce + residual + LayerNorm ----------------
// q = p[0] + p[1] + bias + resid;  sout = q (if non-null);  y = LN(q; g,b)
__global__ __launch_bounds__(256) void ln_fuse(
    const float* __restrict__ p, const float* __restrict__ resid,
    const float* __restrict__ bias, const float* __restrict__ g,
    const float* __restrict__ b, float* __restrict__ sout,
    void* __restrict__ yv, int half_out)
{
    __shared__ float red[256];
    const int row = blockIdx.x;
    const int tid = threadIdx.x;
    const size_t base = (size_t)row * CC;

    float v[4];
    float s = 0.f;
    #pragma unroll
    for (int i = 0; i < 4; i++) {
        int c = tid + i*256;
        float x = p[base + c] + p[PARTSTRIDE + base + c] + bias[c];
        if (resid) x += resid[base + c];
        if (sout)  sout[base + c] = x;
        v[i] = x; s += x;
    }
    red[tid] = s; __syncthreads();
    for (int off = 128; off > 0; off >>= 1) {
        if (tid < off) red[tid] += red[tid + off];
        __syncthreads();
    }
    const float mean = red[0] * (1.f / CC);
    __syncthreads();

    float sq = 0.f;
    #pragma unroll
    for (int i = 0; i < 4; i++) { float d = v[i] - mean; sq += d * d; }
    red[tid] = sq; __syncthreads();
    for (int off = 128; off > 0; off >>= 1) {
        if (tid < off) red[tid] += red[tid + off];
        __syncthreads();
    }
    const float rstd = rsqrtf(red[0] * (1.f / CC) + EPSLN);

    #pragma unroll
    for (int i = 0; i < 4; i++) {
        int c = tid + i*256;
        float o = (v[i] - mean) * rstd * g[c] + b[c];
        if (half_out) ((__half*)yv)[base + c] = __float2half(o);
        else          ((float*)yv)[base + c] = o;
    }
}

// ---------------- fp16 flash attention (unchanged) ----------------
#define SRH 36
__global__ __launch_bounds__(256) void attn_f16(
    const __half* __restrict__ QH, const __half* __restrict__ KV,
    const int* __restrict__ mask, __half* __restrict__ OUT)
{
    extern __shared__ uint32_t sm32[];
    uint32_t* Qs = sm32;
    uint32_t* Ks = Qs + 64*SRH;
    uint32_t* Vs = Ks + 64*SRH;
    uint32_t* Ps = Vs + 64*SRH;
    float*    Mv = (float*)(Ps + 64*SRH);
    float*    hm = Mv + 64;
    float*    hs = hm + 128;

    const int tid  = threadIdx.x;
    const int lane = tid & 31;
    const int warp = tid >> 5;
    const int wq   = warp >> 1;
    const int wk   = warp & 1;
    const int lr   = lane >> 2;
    const int lc   = lane & 3;
    const int b = blockIdx.z, h = blockIdx.y;
    const int q0 = blockIdx.x * 64;

    {
        const __half2 sc = __float2half2_rn(0.125f);
        int r  = tid >> 2;
        int j0 = tid & 3;
        const uint2* src = (const uint2*)(QH + (size_t)(b*NQ + q0 + r)*CC + h*HD);
        #pragma unroll
        for (int i = 0; i < 4; i++) {
            int j = j0 + 4*i;
            uint2 v = src[j];
            __half2 h0 = __hmul2(*(__half2*)&v.x, sc);
            __half2 h1 = __hmul2(*(__half2*)&v.y, sc);
            Qs[r*SRH + 2*j]     = *(uint32_t*)&h0;
            Qs[r*SRH + 2*j + 1] = *(uint32_t*)&h1;
        }
    }

    const int row0 = 16*wq + lr;
    const int row1 = row0 + 8;

    float m0 = -1e30f, m1 = -1e30f, l0 = 0.f, l1 = 0.f;
    float oacc[4][4];
    #pragma unroll
    for (int fn = 0; fn < 4; fn++)
        #pragma unroll
        for (int r = 0; r < 4; r++) oacc[fn][r] = 0.f;

    for (int kc = 0; kc < NC; kc += 64) {
        __syncthreads();

        {
            int r  = tid >> 2;
            int j0 = tid & 3;
            const uint2* srcK = (const uint2*)(KV + (size_t)(b*NC + kc + r)*(2*CC) + h*HD);
            const uint2* srcV = (const uint2*)(KV + (size_t)(b*NC + kc + r)*(2*CC) + CC + h*HD);
            __half* Vh = (__half*)Vs;
            #pragma unroll
            for (int i = 0; i < 4; i++) {
                int j = j0 + 4*i;
                uint2 kv = srcK[j];
                Ks[r*SRH + 2*j]     = kv.x;
                Ks[r*SRH + 2*j + 1] = kv.y;
                uint2 vv = srcV[j];
                __half2 v0 = *(__half2*)&vv.x;
                __half2 v1 = *(__half2*)&vv.y;
                int d0 = 4*j;
                Vh[(d0 + 0)*(2*SRH) + r] = __low2half(v0);
                Vh[(d0 + 1)*(2*SRH) + r] = __high2half(v0);
                Vh[(d0 + 2)*(2*SRH) + r] = __low2half(v1);
                Vh[(d0 + 3)*(2*SRH) + r] = __high2half(v1);
            }
            if (tid < 64)
                Mv[tid] = (mask[b*NC + kc + tid] != 0) ? 0.f : -1e30f;
        }
        __syncthreads();

        float sfr[4][4];
        #pragma unroll
        for (int fn = 0; fn < 4; fn++)
            #pragma unroll
            for (int r = 0; r < 4; r++) sfr[fn][r] = 0.f;

        #pragma unroll
        for (int t = 0; t < 4; t++) {
            const int u0 = 8*t + lc;
            uint32_t a0 = Qs[row0*SRH + u0];
            uint32_t a1 = Qs[row1*SRH + u0];
            uint32_t a2 = Qs[row0*SRH + u0 + 4];
            uint32_t a3 = Qs[row1*SRH + u0 + 4];
            #pragma unroll
            for (int fn = 0; fn < 4; fn++) {
                const uint32_t* p = Ks + (32*wk + 8*fn + lr)*SRH;
                MMA_F16(sfr[fn], a0, a1, a2, a3, p[u0], p[u0 + 4]);
            }
        }

        float mx0 = -1e30f, mx1 = -1e30f;
        float mc0[4], mc1[4];
        #pragma unroll
        for (int fn = 0; fn < 4; fn++) {
            int col = 32*wk + 8*fn + 2*lc;
            mc0[fn] = Mv[col];
            mc1[fn] = Mv[col + 1];
            sfr[fn][0] += mc0[fn]; sfr[fn][1] += mc1[fn];
            sfr[fn][2] += mc0[fn]; sfr[fn][3] += mc1[fn];
            mx0 = fmaxf(mx0, fmaxf(sfr[fn][0], sfr[fn][1]));
            mx1 = fmaxf(mx1, fmaxf(sfr[fn][2], sfr[fn][3]));
        }
        mx0 = fmaxf(mx0, __shfl_xor_sync(0xffffffffu, mx0, 1));
        mx0 = fmaxf(mx0, __shfl_xor_sync(0xffffffffu, mx0, 2));
        mx1 = fmaxf(mx1, __shfl_xor_sync(0xffffffffu, mx1, 1));
        mx1 = fmaxf(mx1, __shfl_xor_sync(0xffffffffu, mx1, 2));
        if (lc == 0) {
            hm[wk*64 + row0] = mx0;
            hm[wk*64 + row1] = mx1;
        }
        __syncthreads();

        const float nm0 = fmaxf(m0, fmaxf(hm[row0], hm[64 + row0]));
        const float nm1 = fmaxf(m1, fmaxf(hm[row1], hm[64 + row1]));
        const float al0 = __expf(m0 - nm0);
        const float al1 = __expf(m1 - nm1);

        float sum0 = 0.f, sum1 = 0.f;
        #pragma unroll
        for (int fn = 0; fn < 4; fn++) {
            float mb0 = (mc0[fn] == 0.f) ? 1.f : 0.f;
            float mb1 = (mc1[fn] == 0.f) ? 1.f : 0.f;
            float p0 = __expf(sfr[fn][0] - nm0) * mb0;
            float p1 = __expf(sfr[fn][1] - nm0) * mb1;
            float p2 = __expf(sfr[fn][2] - nm1) * mb0;
            float p3 = __expf(sfr[fn][3] - nm1) * mb1;
            sum0 += p0 + p1;
            sum1 += p2 + p3;
            int ui = 16*wk + 4*fn + lc;
            __half2 hp0 = __floats2half2_rn(p0, p1);
            __half2 hp1 = __floats2half2_rn(p2, p3);
            Ps[row0*SRH + ui] = *(uint32_t*)&hp0;
            Ps[row1*SRH + ui] = *(uint32_t*)&hp1;
        }
        sum0 += __shfl_xor_sync(0xffffffffu, sum0, 1);
        sum0 += __shfl_xor_sync(0xffffffffu, sum0, 2);
        sum1 += __shfl_xor_sync(0xffffffffu, sum1, 1);
        sum1 += __shfl_xor_sync(0xffffffffu, sum1, 2);
        if (lc == 0) {
            hs[wk*64 + row0] = sum0;
            hs[wk*64 + row1] = sum1;
        }

        #pragma unroll
        for (int fn = 0; fn < 4; fn++) {
            oacc[fn][0] *= al0; oacc[fn][1] *= al0;
            oacc[fn][2] *= al1; oacc[fn][3] *= al1;
        }
        __syncthreads();

        l0 = l0 * al0 + hs[row0] + hs[64 + row0];
        l1 = l1 * al1 + hs[row1] + hs[64 + row1];
        m0 = nm0; m1 = nm1;

        #pragma unroll
        for (int t = 0; t < 4; t++) {
            const int u0 = 8*t + lc;
            uint32_t a0 = Ps[row0*SRH + u0];
            uint32_t a1 = Ps[row1*SRH + u0];
            uint32_t a2 = Ps[row0*SRH + u0 + 4];
            uint32_t a3 = Ps[row1*SRH + u0 + 4];
            #pragma unroll
            for (int fn = 0; fn < 4; fn++) {
                const uint32_t* p = Vs + (32*wk + 8*fn + lr)*SRH;
                MMA_F16(oacc[fn], a0, a1, a2, a3, p[u0], p[u0 + 4]);
            }
        }
    }

    const float il0 = 1.f / l0;
    const float il1 = 1.f / l1;
    #pragma unroll
    for (int fn = 0; fn < 4; fn++) {
        int col = h*HD + 32*wk + 8*fn + 2*lc;
        *(__half2*)(OUT + (size_t)(b*NQ + q0 + row0)*CC + col) =
            __floats2half2_rn(oacc[fn][0]*il0, oacc[fn][1]*il0);
        *(__half2*)(OUT + (size_t)(b*NQ + q0 + row1)*CC + col) =
            __floats2half2_rn(oacc[fn][2]*il1, oacc[fn][3]*il1);
    }
}

// ---------------- orchestration ----------------
extern "C" void kernel_launch(void* const* d_in, const int* in_sizes, int n_in,
                              void* d_out, int out_size)
{
    const float* query   = (const float*)d_in[0];
    const float* context = (const float*)d_in[1];
    const int*   cmask   = (const int*)  d_in[2];
    const float* Wqp   = (const float*)d_in[3];
    const float* bqp   = (const float*)d_in[4];
    const float* Wcp   = (const float*)d_in[5];
    const float* bcp   = (const float*)d_in[6];
    const float* Wq    = (const float*)d_in[7];
    const float* bq    = (const float*)d_in[8];
    const float* Wkv   = (const float*)d_in[9];
    const float* bkv   = (const float*)d_in[10];
    const float* Wo    = (const float*)d_in[11];
    const float* bo    = (const float*)d_in[12];
    const float* g1    = (const float*)d_in[13];
    const float* beta1 = (const float*)d_in[14];
    const float* W1    = (const float*)d_in[15];
    const float* bf1   = (const float*)d_in[16];
    const float* W2    = (const float*)d_in[17];
    const float* bf2   = (const float*)d_in[18];
    const float* g2    = (const float*)d_in[19];
    const float* beta2 = (const float*)d_in[20];
    const float* gf    = (const float*)d_in[21];
    const float* betaf = (const float*)d_in[22];
    float* out = (float*)d_out;

    float  *S0, *S1, *part;
    __half *bufC, *bufQN, *bufQH, *bufKV, *bufO, *bufF;
    __half *rQuery, *rCtx, *rWqp, *rWcp, *rWq, *rWkv, *rWo, *rW1, *rW2;
    cudaGetSymbolAddress((void**)&S0,   g_bufQ);
    cudaGetSymbolAddress((void**)&S1,   g_bufQ2);
    cudaGetSymbolAddress((void**)&part, g_part);
    cudaGetSymbolAddress((void**)&bufC,  g_bufC);
    cudaGetSymbolAddress((void**)&bufQN, g_bufQN);
    cudaGetSymbolAddress((void**)&bufQH, g_bufQH);
    cudaGetSymbolAddress((void**)&bufKV, g_bufKV);
    cudaGetSymbolAddress((void**)&bufO,  g_bufO);
    cudaGetSymbolAddress((void**)&bufF,  g_bufF);
    cudaGetSymbolAddress((void**)&rQuery, g_rQuery);
    cudaGetSymbolAddress((void**)&rCtx,   g_rCtx);
    cudaGetSymbolAddress((void**)&rWqp,   g_rWqp);
    cudaGetSymbolAddress((void**)&rWcp,   g_rWcp);
    cudaGetSymbolAddress((void**)&rWq,    g_rWq);
    cudaGetSymbolAddress((void**)&rWkv,   g_rWkv);
    cudaGetSymbolAddress((void**)&rWo,    g_rWo);
    cudaGetSymbolAddress((void**)&rW1,    g_rW1);
    cudaGetSymbolAddress((void**)&rW2,    g_rW2);

    const int smem_gemm = 4 * 16384;
    cudaFuncSetAttribute(gemm_f16,      cudaFuncAttributeMaxDynamicSharedMemorySize, smem_gemm);
    cudaFuncSetAttribute(gemm_f16_dual, cudaFuncAttributeMaxDynamicSharedMemorySize, smem_gemm);
    const int smem_attn = (4*64*SRH + 64 + 128 + 128) * 4;
    cudaFuncSetAttribute(attn_f16, cudaFuncAttributeMaxDynamicSharedMemorySize, smem_attn);

    const dim3 blk(256);
    const int MQ = B_ * NQ;   // 2048
    const int MC = B_ * NC;   // 8192

    // ---- prep ----
    tohalf<<<(B_*NQ*DQ)/1024, 256>>>(query,   rQuery, B_*NQ*DQ);
    tohalf<<<(B_*NC*DC)/1024, 256>>>(context, rCtx,   B_*NC*DC);
    {
        TTtab tab; int off = 0, i = 0;
        auto add = [&](const float* s, __half* d, int K, int N) {
            tab.p[i] = TTp{s, d, K, N, off};
            off += (N/32) * (K/32); i++;
        };
        add(Wqp, rWqp, DQ, CC);
        add(Wcp, rWcp, DC, CC);
        for (int l = 0; l < LL; l++) {
            add(Wq  + (size_t)l*CC*CC,   rWq  + (size_t)l*CC*CC,   CC, CC);
            add(Wkv + (size_t)l*CC*2*CC, rWkv + (size_t)l*CC*2*CC, CC, 2*CC);
            add(Wo  + (size_t)l*CC*CC,   rWo  + (size_t)l*CC*CC,   CC, CC);
            add(W1  + (size_t)l*CC*FF,   rW1  + (size_t)l*CC*FF,   CC, FF);
        }
        transpose_mega<<<off, dim3(32, 8)>>>(tab);
    }
    {
        TTtab tab; int off = 0, i = 0;
        for (int l = 0; l < LL; l++) {
            tab.p[i] = TTp{W2 + (size_t)l*FF*CC, rW2 + (size_t)l*FF*CC, FF, CC, off};
            off += (CC/32) * (FF/32); i++;
        }
        for (; i < MAXTT; i++) tab.p[i] = tab.p[i-1];
        transpose_mega<<<off, dim3(32, 8)>>>(tab);
    }

    // ---- input projections: dual(Wcp big + Wqp small) ----
    {
        GProb pc { rCtx,   rWcp, bcp, bufC, CC, DC, CC/128, 2 };   // half out
        GProb pq { rQuery, rWqp, bqp, S0,   CC, DQ, CC/128, 0 };   // fp32 out
        int nblk0 = (CC/128) * (MC/128);   // 512
        int nblk1 = (CC/128) * (MQ/128);   // 128
        gemm_f16_dual<<<nblk0 + nblk1, blk, smem_gemm>>>(pc, pq, nblk0);
    }

    // layer-0 first LN (standalone)
    ln_kernel<<<MQ, 256>>>(S0, g1, beta1, bufQN, 1);

    for (int l = 0; l < LL; l++) {
        // dual: Wkv (big) + Wq (small)
        {
            GProb pkv { bufC,  rWkv + (size_t)l*CC*2*CC, bkv + l*2*CC, bufKV, 2*CC, CC, 2*CC/128, 2 };
            GProb pq  { bufQN, rWq  + (size_t)l*CC*CC,   bq  + l*CC,   bufQH, CC,   CC, CC/128,   2 };
            int nblk0 = (2*CC/128) * (MC/128);   // 1024
            int nblk1 = (CC/128) * (MQ/128);     // 128
            gemm_f16_dual<<<nblk0 + nblk1, blk, smem_gemm>>>(pkv, pq, nblk0);
        }

        attn_f16<<<dim3(NQ/64, HH, B_), blk, smem_attn>>>(bufQH, bufKV, cmask, bufO);

        // Wo split-K2 -> partials; fuse: q_mid = S0 + parts + bo ; LN -> QN ; store S1
        gemm_f16<<<dim3(CC/128, MQ/128, 2), blk, smem_gemm>>>(bufO, rWo + (size_t)l*CC*CC, nullptr, nullptr, part, CC, CC, 4);
        ln_fuse<<<MQ, 256>>>(part, S0, bo + l*CC, g2 + l*CC, beta2 + l*CC, S1, bufQN, 1);

        gemm_f16<<<dim3(FF/128, MQ/128, 1), blk, smem_gemm>>>(bufQN, rW1 + (size_t)l*CC*FF, bf1 + l*FF, nullptr, bufF, FF, CC, 3);

        // W2 split-K2 -> partials
        gemm_f16<<<dim3(CC/128, MQ/128, 2), blk, smem_gemm>>>(bufF, rW2 + (size_t)l*FF*CC, nullptr, nullptr, part, CC, FF, 4);
        if (l + 1 < LL) {
            // q_next = S1 + parts + bf2 ; next layer's LN1 -> QN ; store S0
            ln_fuse<<<MQ, 256>>>(part, S1, bf2 + l*CC, g1 + (l+1)*CC, beta1 + (l+1)*CC, S0, bufQN, 1);
        } else {
            // final LN straight to output (fp32)
            ln_fuse<<<MQ, 256>>>(part, S1, bf2 + l*CC, gf, betaf, nullptr, out, 0);
        }
    }
}

// round 10
// speedup vs baseline: 1.5189x; 1.5189x over previous
#include <cuda_runtime.h>
#include <cuda_fp16.h>
#include <math.h>
#include <stdint.h>

#define B_  4
#define NQ  512
#define NC  2048
#define DQ  1024
#define DC  768
#define CC  1024
#define HH  16
#define HD  64
#define LL  2
#define FF  4096
#define EPSLN 1e-5f

// ---------------- scratch ----------------
__device__ float  g_bufQ [B_*NQ*CC];        // residual stream (fp32)
__device__ __half g_bufC [B_*NC*CC];
__device__ __half g_bufQN[B_*NQ*CC];
__device__ __half g_bufQH[B_*NQ*CC];
__device__ __half g_bufKV[B_*NC*2*CC];
__device__ __half g_bufO [B_*NQ*CC];
__device__ __half g_bufF [B_*NQ*FF];
__device__ __half g_rQuery[B_*NQ*DQ];
__device__ __half g_rCtx  [B_*NC*DC];
__device__ __half g_rWqp  [DQ*CC];
__device__ __half g_rWcp  [DC*CC];
__device__ __half g_rWq   [LL*CC*CC];
__device__ __half g_rWkv  [LL*CC*2*CC];
__device__ __half g_rWo   [LL*CC*CC];
__device__ __half g_rW1   [LL*CC*FF];
__device__ __half g_rW2   [LL*FF*CC];

#define MMA_F16(D, a0,a1,a2,a3, b0,b1)                                           \
    asm volatile(                                                                \
        "mma.sync.aligned.m16n8k16.row.col.f32.f16.f16.f32 "                     \
        "{%0,%1,%2,%3}, {%4,%5,%6,%7}, {%8,%9}, {%0,%1,%2,%3};\n"                \
        : "+f"((D)[0]), "+f"((D)[1]), "+f"((D)[2]), "+f"((D)[3])                 \
        : "r"(a0), "r"(a1), "r"(a2), "r"(a3), "r"(b0), "r"(b1))

__device__ __forceinline__ void cp16(unsigned dst, const void* src) {
    asm volatile("cp.async.cg.shared.global [%0], [%1], 16;" :: "r"(dst), "l"(src));
}
__device__ __forceinline__ void cpcommit() { asm volatile("cp.async.commit_group;"); }
__device__ __forceinline__ void cpwait0()  { asm volatile("cp.async.wait_group 0;"); }
__device__ __forceinline__ void cpwait1()  { asm volatile("cp.async.wait_group 1;"); }
__device__ __forceinline__ void cpwait2()  { asm volatile("cp.async.wait_group 2;"); }

// ---------------- prep ----------------
__global__ __launch_bounds__(256) void tohalf(
    const float* __restrict__ src, __half* __restrict__ dst, int n)
{
    int i = (blockIdx.x * 256 + threadIdx.x) * 4;
    if (i < n) {
        float4 v = *(const float4*)(src + i);
        __half2* d = (__half2*)(dst + i);
        d[0] = __floats2half2_rn(v.x, v.y);
        d[1] = __floats2half2_rn(v.z, v.w);
    }
}

#define MAXTT 10
struct TTp { const float* s; __half* d; int K; int N; int blk0; };
struct TTtab { TTp p[MAXTT]; };

__global__ void transpose_mega(TTtab tab)
{
    __shared__ float t[32][33];
    int b = blockIdx.x;
    int i = 0;
    #pragma unroll
    for (int j = 1; j < MAXTT; j++)
        if (b >= tab.p[j].blk0) i = j;
    const TTp P = tab.p[i];
    int lid = b - P.blk0;
    int nb  = P.N >> 5;
    const int n0 = (lid % nb) * 32, k0 = (lid / nb) * 32;
    const int tx = threadIdx.x, ty = threadIdx.y;
    #pragma unroll
    for (int q = 0; q < 4; q++)
        t[ty + 8*q][tx] = P.s[(size_t)(k0 + ty + 8*q) * P.N + n0 + tx];
    __syncthreads();
    #pragma unroll
    for (int q = 0; q < 4; q++)
        P.d[(size_t)(n0 + ty + 8*q) * P.K + k0 + tx] = __float2half(t[tx][ty + 8*q]);
}

// ---------------- fp16 GEMM body (R7-verified inner loop) ----------------
// flags: 1=gelu, 2=half out
__device__ __forceinline__ void gemm_body(
    int bm, int bn, const __half* __restrict__ A,
    const __half* __restrict__ Bt, int K,
    const float* __restrict__ bias, const float* __restrict__ resid,
    void* __restrict__ outv, int N, int flags)
{
    extern __shared__ uint32_t smu[];
    const int tid  = threadIdx.x;
    const int lane = tid & 31;
    const int warp = tid >> 5;
    const int wmi  = warp >> 2;
    const int wni  = warp & 3;
    const int lr   = lane >> 2;
    const int lc   = lane & 3;

    const int srow = tid >> 1;
    const int c0s  = (tid & 1) * 2;
    const int sswz = ((srow >> 1) & 3) << 2;
    const unsigned sbase = (unsigned)__cvta_generic_to_shared(smu);
    unsigned adst[2], bdst[2];
    #pragma unroll
    for (int i = 0; i < 2; i++) {
        int c = c0s + i;
        adst[i] = sbase + (srow*16 + ((4*c) ^ sswz)) * 4u;
        bdst[i] = sbase + 8192u + (srow*16 + ((4*c) ^ sswz)) * 4u;
    }
    const __half* aSrc = A  + (size_t)(bm + srow) * K + 8*c0s;
    const __half* bSrc = Bt + (size_t)(bn + srow) * K + 8*c0s;

    float acc[4][4][4];
    #pragma unroll
    for (int i = 0; i < 4; i++)
        #pragma unroll
        for (int j = 0; j < 4; j++)
            #pragma unroll
            for (int k = 0; k < 4; k++) acc[i][j][k] = 0.f;

    const int T = K >> 5;

    #define STAGE(t) do {                                                        \
        const unsigned boff = ((t) & 3) * 16384u;                                \
        const __half* sa = aSrc + (t) * 32;                                      \
        const __half* sb = bSrc + (t) * 32;                                      \
        cp16(adst[0] + boff, sa);                                                \
        cp16(adst[1] + boff, sa + 8);                                            \
        cp16(bdst[0] + boff, sb);                                                \
        cp16(bdst[1] + boff, sb + 8);                                            \
        cpcommit();                                                              \
    } while (0)

    STAGE(0); STAGE(1); STAGE(2);

    const int fswz = ((lr >> 1) & 3) << 2;
    const int abase0 = (wmi*64 + lr) * 16;
    const int bbase0 = (wni*32 + lr) * 16;

    for (int t = 0; t < T; t++) {
        const int rem = T - 1 - t;
        if (rem >= 2) cpwait2(); else if (rem == 1) cpwait1(); else cpwait0();
        __syncthreads();
        if (t + 3 < T) STAGE(t + 3);

        const uint32_t* as = smu + (t & 3) * 4096;
        const uint32_t* bs = as + 2048;

        #pragma unroll
        for (int t16 = 0; t16 < 2; t16++) {
            const int u0 = (8*t16 + lc) ^ fswz;
            const int u1 = u0 ^ 4;
            uint32_t af[4][4], bf[4][2];
            #pragma unroll
            for (int fm = 0; fm < 4; fm++) {
                const uint32_t* p = as + abase0 + fm*256;
                af[fm][0] = p[u0];
                af[fm][1] = p[128 + u0];
                af[fm][2] = p[u1];
                af[fm][3] = p[128 + u1];
            }
            #pragma unroll
            for (int fn = 0; fn < 4; fn++) {
                const uint32_t* p = bs + bbase0 + fn*128;
                bf[fn][0] = p[u0];
                bf[fn][1] = p[u1];
            }
            #pragma unroll
            for (int fm = 0; fm < 4; fm++)
                #pragma unroll
                for (int fn = 0; fn < 4; fn++)
                    MMA_F16(acc[fm][fn], af[fm][0], af[fm][1], af[fm][2], af[fm][3],
                            bf[fn][0], bf[fn][1]);
        }
    }
    #undef STAGE

    const int do_gelu  = flags & 1;
    const int half_out = flags & 2;
    #pragma unroll
    for (int fm = 0; fm < 4; fm++) {
        #pragma unroll
        for (int fn = 0; fn < 4; fn++) {
            int row = bm + wmi*64 + fm*16 + lr;
            int col = bn + wni*32 + fn*8 + 2*lc;
            float2 bv = *(const float2*)(bias + col);

            float v0 = acc[fm][fn][0] + bv.x;
            float v1 = acc[fm][fn][1] + bv.y;
            float v2 = acc[fm][fn][2] + bv.x;
            float v3 = acc[fm][fn][3] + bv.y;
            if (do_gelu) {
                v0 = 0.5f * v0 * (1.f + erff(v0 * 0.70710678118654752f));
                v1 = 0.5f * v1 * (1.f + erff(v1 * 0.70710678118654752f));
                v2 = 0.5f * v2 * (1.f + erff(v2 * 0.70710678118654752f));
                v3 = 0.5f * v3 * (1.f + erff(v3 * 0.70710678118654752f));
            }
            if (resid) {
                float2 r0 = *(const float2*)(resid + (size_t)row * N + col);
                float2 r1 = *(const float2*)(resid + (size_t)(row + 8) * N + col);
                v0 += r0.x; v1 += r0.y; v2 += r1.x; v3 += r1.y;
            }
            if (half_out) {
                __half* o = (__half*)outv;
                *(__half2*)(o + (size_t)row * N + col)       = __floats2half2_rn(v0, v1);
                *(__half2*)(o + (size_t)(row + 8) * N + col) = __floats2half2_rn(v2, v3);
            } else {
                float* o = (float*)outv;
                *(float2*)(o + (size_t)row * N + col)        = make_float2(v0, v1);
                *(float2*)(o + (size_t)(row + 8) * N + col)  = make_float2(v2, v3);
            }
        }
    }
}

__global__ __launch_bounds__(256, 2) void gemm_f16(
    const __half* __restrict__ A, const __half* __restrict__ Bt,
    const float* __restrict__ bias, const float* __restrict__ resid,
    void* __restrict__ outv, int N, int K, int flags)
{
    gemm_body(blockIdx.y * 128, blockIdx.x * 128, A, Bt, K, bias, resid, outv, N, flags);
}

struct GProb { const __half* A; const __half* Bt; const float* bias;
               const float* resid; void* out; int N; int K; int gx; int flags; };
__global__ __launch_bounds__(256, 2) void gemm_f16_dual(GProb p0, GProb p1, int nblk0)
{
    int b = blockIdx.x;
    if (b < nblk0) {
        gemm_body((b / p0.gx) * 128, (b % p0.gx) * 128, p0.A, p0.Bt, p0.K,
                  p0.bias, p0.resid, p0.out, p0.N, p0.flags);
    } else {
        b -= nblk0;
        gemm_body((b / p1.gx) * 128, (b % p1.gx) * 128, p1.A, p1.Bt, p1.K,
                  p1.bias, p1.resid, p1.out, p1.N, p1.flags);
    }
}

// ---------------- LayerNorm ----------------
__global__ __launch_bounds__(256) void ln_kernel(
    const float* __restrict__ x, const float* __restrict__ g,
    const float* __restrict__ b, void* __restrict__ yv, int half_out)
{
    __shared__ float red[256];
    const int row = blockIdx.x;
    const int tid = threadIdx.x;
    const float* xr = x + (size_t)row * CC;

    float v[4];
    float s = 0.f;
    #pragma unroll
    for (int i = 0; i < 4; i++) { v[i] = xr[tid + i*256]; s += v[i]; }
    red[tid] = s; __syncthreads();
    for (int off = 128; off > 0; off >>= 1) {
        if (tid < off) red[tid] += red[tid + off];
        __syncthreads();
    }
    const float mean = red[0] * (1.f / CC);
    __syncthreads();

    float sq = 0.f;
    #pragma unroll
    for (int i = 0; i < 4; i++) { float d = v[i] - mean; sq += d * d; }
    red[tid] = sq; __syncthreads();
    for (int off = 128; off > 0; off >>= 1) {
        if (tid < off) red[tid] += red[tid + off];
        __syncthreads();
    }
    const float rstd = rsqrtf(red[0] * (1.f / CC) + EPSLN);

    #pragma unroll
    for (int i = 0; i < 4; i++) {
        int c = tid + i*256;
        float o = (v[i] - mean) * rstd * g[c] + b[c];
        if (half_out) ((__half*)yv)[(size_t)row * CC + c] = __float2half(o);
        else          ((float*)yv)[(size_t)row * CC + c] = o;
    }
}

// ---------------- fp16 flash attention (R7-verified) ----------------
#define SRH 36
__global__ __launch_bounds__(256) void attn_f16(
    const __half* __restrict__ QH, const __half* __restrict__ KV,
    const int* __restrict__ mask, __half* __restrict__ OUT)
{
    extern __shared__ uint32_t sm32[];
    uint32_t* Qs = sm32;
    uint32_t* Ks = Qs + 64*SRH;
    uint32_t* Vs = Ks + 64*SRH;
    uint32_t* Ps = Vs + 64*SRH;
    float*    Mv = (float*)(Ps + 64*SRH);
    float*    hm = Mv + 64;
    float*    hs = hm + 128;

    const int tid  = threadIdx.x;
    const int lane = tid & 31;
    const int warp = tid >> 5;
    const int wq   = warp >> 1;
    const int wk   = warp & 1;
    const int lr   = lane >> 2;
    const int lc   = lane & 3;
    const int b = blockIdx.z, h = blockIdx.y;
    const int q0 = blockIdx.x * 64;

    {
        const __half2 sc = __float2half2_rn(0.125f);
        int r  = tid >> 2;
        int j0 = tid & 3;
        const uint2* src = (const uint2*)(QH + (size_t)(b*NQ + q0 + r)*CC + h*HD);
        #pragma unroll
        for (int i = 0; i < 4; i++) {
            int j = j0 + 4*i;
            uint2 v = src[j];
            __half2 h0 = __hmul2(*(__half2*)&v.x, sc);
            __half2 h1 = __hmul2(*(__half2*)&v.y, sc);
            Qs[r*SRH + 2*j]     = *(uint32_t*)&h0;
            Qs[r*SRH + 2*j + 1] = *(uint32_t*)&h1;
        }
    }

    const int row0 = 16*wq + lr;
    const int row1 = row0 + 8;

    float m0 = -1e30f, m1 = -1e30f, l0 = 0.f, l1 = 0.f;
    float oacc[4][4];
    #pragma unroll
    for (int fn = 0; fn < 4; fn++)
        #pragma unroll
        for (int r = 0; r < 4; r++) oacc[fn][r] = 0.f;

    for (int kc = 0; kc < NC; kc += 64) {
        __syncthreads();

        {
            int r  = tid >> 2;
            int j0 = tid & 3;
            const uint2* srcK = (const uint2*)(KV + (size_t)(b*NC + kc + r)*(2*CC) + h*HD);
            const uint2* srcV = (const uint2*)(KV + (size_t)(b*NC + kc + r)*(2*CC) + CC + h*HD);
            __half* Vh = (__half*)Vs;
            #pragma unroll
            for (int i = 0; i < 4; i++) {
                int j = j0 + 4*i;
                uint2 kv = srcK[j];
                Ks[r*SRH + 2*j]     = kv.x;
                Ks[r*SRH + 2*j + 1] = kv.y;
                uint2 vv = srcV[j];
                __half2 v0 = *(__half2*)&vv.x;
                __half2 v1 = *(__half2*)&vv.y;
                int d0 = 4*j;
                Vh[(d0 + 0)*(2*SRH) + r] = __low2half(v0);
                Vh[(d0 + 1)*(2*SRH) + r] = __high2half(v0);
                Vh[(d0 + 2)*(2*SRH) + r] = __low2half(v1);
                Vh[(d0 + 3)*(2*SRH) + r] = __high2half(v1);
            }
            if (tid < 64)
                Mv[tid] = (mask[b*NC + kc + tid] != 0) ? 0.f : -1e30f;
        }
        __syncthreads();

        float sfr[4][4];
        #pragma unroll
        for (int fn = 0; fn < 4; fn++)
            #pragma unroll
            for (int r = 0; r < 4; r++) sfr[fn][r] = 0.f;

        #pragma unroll
        for (int t = 0; t < 4; t++) {
            const int u0 = 8*t + lc;
            uint32_t a0 = Qs[row0*SRH + u0];
            uint32_t a1 = Qs[row1*SRH + u0];
            uint32_t a2 = Qs[row0*SRH + u0 + 4];
            uint32_t a3 = Qs[row1*SRH + u0 + 4];
            #pragma unroll
            for (int fn = 0; fn < 4; fn++) {
                const uint32_t* p = Ks + (32*wk + 8*fn + lr)*SRH;
                MMA_F16(sfr[fn], a0, a1, a2, a3, p[u0], p[u0 + 4]);
            }
        }

        float mx0 = -1e30f, mx1 = -1e30f;
        float mc0[4], mc1[4];
        #pragma unroll
        for (int fn = 0; fn < 4; fn++) {
            int col = 32*wk + 8*fn + 2*lc;
            mc0[fn] = Mv[col];
            mc1[fn] = Mv[col + 1];
            sfr[fn][0] += mc0[fn]; sfr[fn][1] += mc1[fn];
            sfr[fn][2] += mc0[fn]; sfr[fn][3] += mc1[fn];
            mx0 = fmaxf(mx0, fmaxf(sfr[fn][0], sfr[fn][1]));
            mx1 = fmaxf(mx1, fmaxf(sfr[fn][2], sfr[fn][3]));
        }
        mx0 = fmaxf(mx0, __shfl_xor_sync(0xffffffffu, mx0, 1));
        mx0 = fmaxf(mx0, __shfl_xor_sync(0xffffffffu, mx0, 2));
        mx1 = fmaxf(mx1, __shfl_xor_sync(0xffffffffu, mx1, 1));
        mx1 = fmaxf(mx1, __shfl_xor_sync(0xffffffffu, mx1, 2));
        if (lc == 0) {
            hm[wk*64 + row0] = mx0;
            hm[wk*64 + row1] = mx1;
        }
        __syncthreads();

        const float nm0 = fmaxf(m0, fmaxf(hm[row0], hm[64 + row0]));
        const float nm1 = fmaxf(m1, fmaxf(hm[row1], hm[64 + row1]));
        const float al0 = __expf(m0 - nm0);
        const float al1 = __expf(m1 - nm1);

        float sum0 = 0.f, sum1 = 0.f;
        #pragma unroll
        for (int fn = 0; fn < 4; fn++) {
            float mb0 = (mc0[fn] == 0.f) ? 1.f : 0.f;
            float mb1 = (mc1[fn] == 0.f) ? 1.f : 0.f;
            float p0 = __expf(sfr[fn][0] - nm0) * mb0;
            float p1 = __expf(sfr[fn][1] - nm0) * mb1;
            float p2 = __expf(sfr[fn][2] - nm1) * mb0;
            float p3 = __expf(sfr[fn][3] - nm1) * mb1;
            sum0 += p0 + p1;
            sum1 += p2 + p3;
            int ui = 16*wk + 4*fn + lc;
            __half2 hp0 = __floats2half2_rn(p0, p1);
            __half2 hp1 = __floats2half2_rn(p2, p3);
            Ps[row0*SRH + ui] = *(uint32_t*)&hp0;
            Ps[row1*SRH + ui] = *(uint32_t*)&hp1;
        }
        sum0 += __shfl_xor_sync(0xffffffffu, sum0, 1);
        sum0 += __shfl_xor_sync(0xffffffffu, sum0, 2);
        sum1 += __shfl_xor_sync(0xffffffffu, sum1, 1);
        sum1 += __shfl_xor_sync(0xffffffffu, sum1, 2);
        if (lc == 0) {
            hs[wk*64 + row0] = sum0;
            hs[wk*64 + row1] = sum1;
        }

        #pragma unroll
        for (int fn = 0; fn < 4; fn++) {
            oacc[fn][0] *= al0; oacc[fn][1] *= al0;
            oacc[fn][2] *= al1; oacc[fn][3] *= al1;
        }
        __syncthreads();

        l0 = l0 * al0 + hs[row0] + hs[64 + row0];
        l1 = l1 * al1 + hs[row1] + hs[64 + row1];
        m0 = nm0; m1 = nm1;

        #pragma unroll
        for (int t = 0; t < 4; t++) {
            const int u0 = 8*t + lc;
            uint32_t a0 = Ps[row0*SRH + u0];
            uint32_t a1 = Ps[row1*SRH + u0];
            uint32_t a2 = Ps[row0*SRH + u0 + 4];
            uint32_t a3 = Ps[row1*SRH + u0 + 4];
            #pragma unroll
            for (int fn = 0; fn < 4; fn++) {
                const uint32_t* p = Vs + (32*wk + 8*fn + lr)*SRH;
                MMA_F16(oacc[fn], a0, a1, a2, a3, p[u0], p[u0 + 4]);
            }
        }
    }

    const float il0 = 1.f / l0;
    const float il1 = 1.f / l1;
    #pragma unroll
    for (int fn = 0; fn < 4; fn++) {
        int col = h*HD + 32*wk + 8*fn + 2*lc;
        *(__half2*)(OUT + (size_t)(b*NQ + q0 + row0)*CC + col) =
            __floats2half2_rn(oacc[fn][0]*il0, oacc[fn][1]*il0);
        *(__half2*)(OUT + (size_t)(b*NQ + q0 + row1)*CC + col) =
            __floats2half2_rn(oacc[fn][2]*il1, oacc[fn][3]*il1);
    }
}

// ---------------- orchestration ----------------
extern "C" void kernel_launch(void* const* d_in, const int* in_sizes, int n_in,
                              void* d_out, int out_size)
{
    const float* query   = (const float*)d_in[0];
    const float* context = (const float*)d_in[1];
    const int*   cmask   = (const int*)  d_in[2];
    const float* Wqp   = (const float*)d_in[3];
    const float* bqp   = (const float*)d_in[4];
    const float* Wcp   = (const float*)d_in[5];
    const float* bcp   = (const float*)d_in[6];
    const float* Wq    = (const float*)d_in[7];
    const float* bq    = (const float*)d_in[8];
    const float* Wkv   = (const float*)d_in[9];
    const float* bkv   = (const float*)d_in[10];
    const float* Wo    = (const float*)d_in[11];
    const float* bo    = (const float*)d_in[12];
    const float* g1    = (const float*)d_in[13];
    const float* beta1 = (const float*)d_in[14];
    const float* W1    = (const float*)d_in[15];
    const float* bf1   = (const float*)d_in[16];
    const float* W2    = (const float*)d_in[17];
    const float* bf2   = (const float*)d_in[18];
    const float* g2    = (const float*)d_in[19];
    const float* beta2 = (const float*)d_in[20];
    const float* gf    = (const float*)d_in[21];
    const float* betaf = (const float*)d_in[22];
    float* out = (float*)d_out;

    float  *bufQ;
    __half *bufC, *bufQN, *bufQH, *bufKV, *bufO, *bufF;
    __half *rQuery, *rCtx, *rWqp, *rWcp, *rWq, *rWkv, *rWo, *rW1, *rW2;
    cudaGetSymbolAddress((void**)&bufQ,  g_bufQ);
    cudaGetSymbolAddress((void**)&bufC,  g_bufC);
    cudaGetSymbolAddress((void**)&bufQN, g_bufQN);
    cudaGetSymbolAddress((void**)&bufQH, g_bufQH);
    cudaGetSymbolAddress((void**)&bufKV, g_bufKV);
    cudaGetSymbolAddress((void**)&bufO,  g_bufO);
    cudaGetSymbolAddress((void**)&bufF,  g_bufF);
    cudaGetSymbolAddress((void**)&rQuery, g_rQuery);
    cudaGetSymbolAddress((void**)&rCtx,   g_rCtx);
    cudaGetSymbolAddress((void**)&rWqp,   g_rWqp);
    cudaGetSymbolAddress((void**)&rWcp,   g_rWcp);
    cudaGetSymbolAddress((void**)&rWq,    g_rWq);
    cudaGetSymbolAddress((void**)&rWkv,   g_rWkv);
    cudaGetSymbolAddress((void**)&rWo,    g_rWo);
    cudaGetSymbolAddress((void**)&rW1,    g_rW1);
    cudaGetSymbolAddress((void**)&rW2,    g_rW2);

    const int smem_gemm = 4 * 16384;
    cudaFuncSetAttribute(gemm_f16,      cudaFuncAttributeMaxDynamicSharedMemorySize, smem_gemm);
    cudaFuncSetAttribute(gemm_f16_dual, cudaFuncAttributeMaxDynamicSharedMemorySize, smem_gemm);
    const int smem_attn = (4*64*SRH + 64 + 128 + 128) * 4;
    cudaFuncSetAttribute(attn_f16, cudaFuncAttributeMaxDynamicSharedMemorySize, smem_attn);

    const dim3 blk(256);
    const int MQ = B_ * NQ;   // 2048
    const int MC = B_ * NC;   // 8192

    // ---- prep: halve activations; transpose+halve weights (2 mega launches) ----
    tohalf<<<(B_*NQ*DQ)/1024, 256>>>(query,   rQuery, B_*NQ*DQ);
    tohalf<<<(B_*NC*DC)/1024, 256>>>(context, rCtx,   B_*NC*DC);
    {
        TTtab tab; int off = 0, i = 0;
        auto add = [&](const float* s, __half* d, int K, int N) {
            tab.p[i] = TTp{s, d, K, N, off};
            off += (N/32) * (K/32); i++;
        };
        add(Wqp, rWqp, DQ, CC);
        add(Wcp, rWcp, DC, CC);
        for (int l = 0; l < LL; l++) {
            add(Wq  + (size_t)l*CC*CC,   rWq  + (size_t)l*CC*CC,   CC, CC);
            add(Wkv + (size_t)l*CC*2*CC, rWkv + (size_t)l*CC*2*CC, CC, 2*CC);
            add(Wo  + (size_t)l*CC*CC,   rWo  + (size_t)l*CC*CC,   CC, CC);
            add(W1  + (size_t)l*CC*FF,   rW1  + (size_t)l*CC*FF,   CC, FF);
        }
        transpose_mega<<<off, dim3(32, 8)>>>(tab);
    }
    {
        TTtab tab; int off = 0, i = 0;
        for (int l = 0; l < LL; l++) {
            tab.p[i] = TTp{W2 + (size_t)l*FF*CC, rW2 + (size_t)l*FF*CC, FF, CC, off};
            off += (CC/32) * (FF/32); i++;
        }
        for (; i < MAXTT; i++) tab.p[i] = tab.p[i-1];
        transpose_mega<<<off, dim3(32, 8)>>>(tab);
    }

    // ---- input projections (R7 schedule) ----
    gemm_f16<<<dim3(CC/128, MQ/128), blk, smem_gemm>>>(rQuery, rWqp, bqp, nullptr, bufQ, CC, DQ, 0);
    gemm_f16<<<dim3(CC/128, MC/128), blk, smem_gemm>>>(rCtx,   rWcp, bcp, nullptr, bufC, CC, DC, 2);

    for (int l = 0; l < LL; l++) {
        ln_kernel<<<MQ, 256>>>(bufQ, g1 + l*CC, beta1 + l*CC, bufQN, 1);

        // dual: Wkv (big) + Wq (small)
        {
            GProb pkv { bufC,  rWkv + (size_t)l*CC*2*CC, bkv + l*2*CC, nullptr, bufKV, 2*CC, CC, 2*CC/128, 2 };
            GProb pq  { bufQN, rWq  + (size_t)l*CC*CC,   bq  + l*CC,   nullptr, bufQH, CC,   CC, CC/128,   2 };
            int nblk0 = (2*CC/128) * (MC/128);   // 1024
            int nblk1 = (CC/128) * (MQ/128);     // 128
            gemm_f16_dual<<<nblk0 + nblk1, blk, smem_gemm>>>(pkv, pq, nblk0);
        }

        attn_f16<<<dim3(NQ/64, HH, B_), blk, smem_attn>>>(bufQH, bufKV, cmask, bufO);

        gemm_f16<<<dim3(CC/128, MQ/128), blk, smem_gemm>>>(bufO, rWo + (size_t)l*CC*CC, bo + l*CC, bufQ, bufQ, CC, CC, 0);

        ln_kernel<<<MQ, 256>>>(bufQ, g2 + l*CC, beta2 + l*CC, bufQN, 1);

        gemm_f16<<<dim3(FF/128, MQ/128), blk, smem_gemm>>>(bufQN, rW1 + (size_t)l*CC*FF, bf1 + l*FF, nullptr, bufF, FF, CC, 3);
        gemm_f16<<<dim3(CC/128, MQ/128), blk, smem_gemm>>>(bufF,  rW2 + (size_t)l*FF*CC, bf2 + l*CC, bufQ,   bufQ, CC, FF, 0);
    }
    ln_kernel<<<MQ, 256>>>(bufQ, gf, betaf, out, 0);
}

// round 11
// speedup vs baseline: 1.6492x; 1.0858x over previous
#include <cuda_runtime.h>
#include <cuda_fp16.h>
#include <math.h>
#include <stdint.h>

#define B_  4
#define NQ  512
#define NC  2048
#define DQ  1024
#define DC  768
#define CC  1024
#define HH  16
#define HD  64
#define LL  2
#define FF  4096
#define EPSLN 1e-5f

// ---------------- scratch ----------------
__device__ float  g_bufQ [B_*NQ*CC];        // residual stream (fp32)
__device__ __half g_bufC [B_*NC*CC];
__device__ __half g_bufQN[B_*NQ*CC];
__device__ __half g_bufQH[B_*NQ*CC];
__device__ __half g_bufKV[B_*NC*2*CC];
__device__ __half g_bufO [B_*NQ*CC];
__device__ __half g_bufF [B_*NQ*FF];
__device__ __half g_rQuery[B_*NQ*DQ];
__device__ __half g_rCtx  [B_*NC*DC];
__device__ __half g_rWqp  [DQ*CC];
__device__ __half g_rWcp  [DC*CC];
__device__ __half g_rWq   [LL*CC*CC];
__device__ __half g_rWkv  [LL*CC*2*CC];
__device__ __half g_rWo   [LL*CC*CC];
__device__ __half g_rW1   [LL*CC*FF];
__device__ __half g_rW2   [LL*FF*CC];

#define MMA_F16(D, a0,a1,a2,a3, b0,b1)                                           \
    asm volatile(                                                                \
        "mma.sync.aligned.m16n8k16.row.col.f32.f16.f16.f32 "                     \
        "{%0,%1,%2,%3}, {%4,%5,%6,%7}, {%8,%9}, {%0,%1,%2,%3};\n"                \
        : "+f"((D)[0]), "+f"((D)[1]), "+f"((D)[2]), "+f"((D)[3])                 \
        : "r"(a0), "r"(a1), "r"(a2), "r"(a3), "r"(b0), "r"(b1))

__device__ __forceinline__ void ldsm_x4(uint32_t* r, unsigned addr) {
    asm volatile("ldmatrix.sync.aligned.m8n8.x4.shared.b16 {%0,%1,%2,%3}, [%4];"
        : "=r"(r[0]), "=r"(r[1]), "=r"(r[2]), "=r"(r[3]) : "r"(addr));
}

__device__ __forceinline__ void cp16(unsigned dst, const void* src) {
    asm volatile("cp.async.cg.shared.global [%0], [%1], 16;" :: "r"(dst), "l"(src));
}
__device__ __forceinline__ void cpcommit() { asm volatile("cp.async.commit_group;"); }
__device__ __forceinline__ void cpwait0()  { asm volatile("cp.async.wait_group 0;"); }
__device__ __forceinline__ void cpwait1()  { asm volatile("cp.async.wait_group 1;"); }
__device__ __forceinline__ void cpwait2()  { asm volatile("cp.async.wait_group 2;"); }

// ---------------- prep ----------------
__global__ __launch_bounds__(256) void tohalf(
    const float* __restrict__ src, __half* __restrict__ dst, int n)
{
    int i = (blockIdx.x * 256 + threadIdx.x) * 4;
    if (i < n) {
        float4 v = *(const float4*)(src + i);
        __half2* d = (__half2*)(dst + i);
        d[0] = __floats2half2_rn(v.x, v.y);
        d[1] = __floats2half2_rn(v.z, v.w);
    }
}

#define MAXTT 10
struct TTp { const float* s; __half* d; int K; int N; int blk0; };
struct TTtab { TTp p[MAXTT]; };

__global__ void transpose_mega(TTtab tab)
{
    __shared__ float t[32][33];
    int b = blockIdx.x;
    int i = 0;
    #pragma unroll
    for (int j = 1; j < MAXTT; j++)
        if (b >= tab.p[j].blk0) i = j;
    const TTp P = tab.p[i];
    int lid = b - P.blk0;
    int nb  = P.N >> 5;
    const int n0 = (lid % nb) * 32, k0 = (lid / nb) * 32;
    const int tx = threadIdx.x, ty = threadIdx.y;
    #pragma unroll
    for (int q = 0; q < 4; q++)
        t[ty + 8*q][tx] = P.s[(size_t)(k0 + ty + 8*q) * P.N + n0 + tx];
    __syncthreads();
    #pragma unroll
    for (int q = 0; q < 4; q++)
        P.d[(size_t)(n0 + ty + 8*q) * P.K + k0 + tx] = __float2half(t[tx][ty + 8*q]);
}

// ---------------- fp16 GEMM body (ldmatrix fragment loads) ----------------
// flags: 1=gelu, 2=half out
__device__ __forceinline__ void gemm_body(
    int bm, int bn, const __half* __restrict__ A,
    const __half* __restrict__ Bt, int K,
    const float* __restrict__ bias, const float* __restrict__ resid,
    void* __restrict__ outv, int N, int flags)
{
    extern __shared__ uint32_t smu[];
    const int tid  = threadIdx.x;
    const int lane = tid & 31;
    const int warp = tid >> 5;
    const int wmi  = warp >> 2;
    const int wni  = warp & 3;
    const int lr   = lane >> 2;
    const int lc   = lane & 3;

    const int srow = tid >> 1;
    const int c0s  = (tid & 1) * 2;
    const int sswz = ((srow >> 1) & 3) << 2;
    const unsigned sbase = (unsigned)__cvta_generic_to_shared(smu);
    unsigned adst[2], bdst[2];
    #pragma unroll
    for (int i = 0; i < 2; i++) {
        int c = c0s + i;
        adst[i] = sbase + (srow*16 + ((4*c) ^ sswz)) * 4u;
        bdst[i] = sbase + 8192u + (srow*16 + ((4*c) ^ sswz)) * 4u;
    }
    const __half* aSrc = A  + (size_t)(bm + srow) * K + 8*c0s;
    const __half* bSrc = Bt + (size_t)(bn + srow) * K + 8*c0s;

    // ldmatrix per-lane fragment addresses
    const int mi  = lane >> 3;        // matrix index 0..3
    const int mi0 = mi & 1, mi1 = mi >> 1;
    const int rw  = lane & 7;
    unsigned aaddr[4][2], baddr[2][2];
    #pragma unroll
    for (int fm = 0; fm < 4; fm++) {
        int row = wmi*64 + fm*16 + mi0*8 + rw;
        int swz = ((row >> 1) & 3) << 2;
        #pragma unroll
        for (int u = 0; u < 2; u++)
            aaddr[fm][u] = sbase + (unsigned)(row*16 + ((8*u + 4*mi1) ^ swz)) * 4u;
    }
    #pragma unroll
    for (int g = 0; g < 2; g++) {
        int row = wni*32 + (2*g + mi1)*8 + rw;
        int swz = ((row >> 1) & 3) << 2;
        #pragma unroll
        for (int u = 0; u < 2; u++)
            baddr[g][u] = sbase + 8192u + (unsigned)(row*16 + ((8*u + 4*mi0) ^ swz)) * 4u;
    }

    float acc[4][4][4];
    #pragma unroll
    for (int i = 0; i < 4; i++)
        #pragma unroll
        for (int j = 0; j < 4; j++)
            #pragma unroll
            for (int k = 0; k < 4; k++) acc[i][j][k] = 0.f;

    const int T = K >> 5;

    #define STAGE(t) do {                                                        \
        const unsigned boff = ((t) & 3) * 16384u;                                \
        const __half* sa = aSrc + (t) * 32;                                      \
        const __half* sb = bSrc + (t) * 32;                                      \
        cp16(adst[0] + boff, sa);                                                \
        cp16(adst[1] + boff, sa + 8);                                            \
        cp16(bdst[0] + boff, sb);                                                \
        cp16(bdst[1] + boff, sb + 8);                                            \
        cpcommit();                                                              \
    } while (0)

    STAGE(0); STAGE(1); STAGE(2);

    for (int t = 0; t < T; t++) {
        const int rem = T - 1 - t;
        if (rem >= 2) cpwait2(); else if (rem == 1) cpwait1(); else cpwait0();
        __syncthreads();
        if (t + 3 < T) STAGE(t + 3);

        const unsigned boff = (t & 3) * 16384u;

        #pragma unroll
        for (int t16 = 0; t16 < 2; t16++) {
            uint32_t af[4][4], bf[2][4];
            #pragma unroll
            for (int fm = 0; fm < 4; fm++) ldsm_x4(af[fm], aaddr[fm][t16] + boff);
            #pragma unroll
            for (int g = 0; g < 2; g++)  ldsm_x4(bf[g],  baddr[g][t16] + boff);
            #pragma unroll
            for (int fm = 0; fm < 4; fm++)
                #pragma unroll
                for (int fn = 0; fn < 4; fn++)
                    MMA_F16(acc[fm][fn], af[fm][0], af[fm][1], af[fm][2], af[fm][3],
                            bf[fn >> 1][(fn & 1) * 2], bf[fn >> 1][(fn & 1) * 2 + 1]);
        }
    }
    #undef STAGE

    const int do_gelu  = flags & 1;
    const int half_out = flags & 2;
    #pragma unroll
    for (int fm = 0; fm < 4; fm++) {
        #pragma unroll
        for (int fn = 0; fn < 4; fn++) {
            int row = bm + wmi*64 + fm*16 + lr;
            int col = bn + wni*32 + fn*8 + 2*lc;
            float2 bv = *(const float2*)(bias + col);

            float v0 = acc[fm][fn][0] + bv.x;
            float v1 = acc[fm][fn][1] + bv.y;
            float v2 = acc[fm][fn][2] + bv.x;
            float v3 = acc[fm][fn][3] + bv.y;
            if (do_gelu) {
                v0 = 0.5f * v0 * (1.f + erff(v0 * 0.70710678118654752f));
                v1 = 0.5f * v1 * (1.f + erff(v1 * 0.70710678118654752f));
                v2 = 0.5f * v2 * (1.f + erff(v2 * 0.70710678118654752f));
                v3 = 0.5f * v3 * (1.f + erff(v3 * 0.70710678118654752f));
            }
            if (resid) {
                float2 r0 = *(const float2*)(resid + (size_t)row * N + col);
                float2 r1 = *(const float2*)(resid + (size_t)(row + 8) * N + col);
                v0 += r0.x; v1 += r0.y; v2 += r1.x; v3 += r1.y;
            }
            if (half_out) {
                __half* o = (__half*)outv;
                *(__half2*)(o + (size_t)row * N + col)       = __floats2half2_rn(v0, v1);
                *(__half2*)(o + (size_t)(row + 8) * N + col) = __floats2half2_rn(v2, v3);
            } else {
                float* o = (float*)outv;
                *(float2*)(o + (size_t)row * N + col)        = make_float2(v0, v1);
                *(float2*)(o + (size_t)(row + 8) * N + col)  = make_float2(v2, v3);
            }
        }
    }
}

__global__ __launch_bounds__(256, 2) void gemm_f16(
    const __half* __restrict__ A, const __half* __restrict__ Bt,
    const float* __restrict__ bias, const float* __restrict__ resid,
    void* __restrict__ outv, int N, int K, int flags)
{
    gemm_body(blockIdx.y * 128, blockIdx.x * 128, A, Bt, K, bias, resid, outv, N, flags);
}

struct GProb { const __half* A; const __half* Bt; const float* bias;
               const float* resid; void* out; int N; int K; int gx; int flags; };
__global__ __launch_bounds__(256, 2) void gemm_f16_dual(GProb p0, GProb p1, int nblk0)
{
    int b = blockIdx.x;
    if (b < nblk0) {
        gemm_body((b / p0.gx) * 128, (b % p0.gx) * 128, p0.A, p0.Bt, p0.K,
                  p0.bias, p0.resid, p0.out, p0.N, p0.flags);
    } else {
        b -= nblk0;
        gemm_body((b / p1.gx) * 128, (b % p1.gx) * 128, p1.A, p1.Bt, p1.K,
                  p1.bias, p1.resid, p1.out, p1.N, p1.flags);
    }
}

// ---------------- LayerNorm ----------------
__global__ __launch_bounds__(256) void ln_kernel(
    const float* __restrict__ x, const float* __restrict__ g,
    const float* __restrict__ b, void* __restrict__ yv, int half_out)
{
    __shared__ float red[256];
    const int row = blockIdx.x;
    const int tid = threadIdx.x;
    const float* xr = x + (size_t)row * CC;

    float v[4];
    float s = 0.f;
    #pragma unroll
    for (int i = 0; i < 4; i++) { v[i] = xr[tid + i*256]; s += v[i]; }
    red[tid] = s; __syncthreads();
    for (int off = 128; off > 0; off >>= 1) {
        if (tid < off) red[tid] += red[tid + off];
        __syncthreads();
    }
    const float mean = red[0] * (1.f / CC);
    __syncthreads();

    float sq = 0.f;
    #pragma unroll
    for (int i = 0; i < 4; i++) { float d = v[i] - mean; sq += d * d; }
    red[tid] = sq; __syncthreads();
    for (int off = 128; off > 0; off >>= 1) {
        if (tid < off) red[tid] += red[tid + off];
        __syncthreads();
    }
    const float rstd = rsqrtf(red[0] * (1.f / CC) + EPSLN);

    #pragma unroll
    for (int i = 0; i < 4; i++) {
        int c = tid + i*256;
        float o = (v[i] - mean) * rstd * g[c] + b[c];
        if (half_out) ((__half*)yv)[(size_t)row * CC + c] = __float2half(o);
        else          ((float*)yv)[(size_t)row * CC + c] = o;
    }
}

// ---------------- fp16 flash attention (ldmatrix fragment loads) ----------------
#define SRH 36
__global__ __launch_bounds__(256) void attn_f16(
    const __half* __restrict__ QH, const __half* __restrict__ KV,
    const int* __restrict__ mask, __half* __restrict__ OUT)
{
    extern __shared__ uint32_t sm32[];
    uint32_t* Qs = sm32;
    uint32_t* Ks = Qs + 64*SRH;
    uint32_t* Vs = Ks + 64*SRH;
    uint32_t* Ps = Vs + 64*SRH;
    float*    Mv = (float*)(Ps + 64*SRH);
    float*    hm = Mv + 64;
    float*    hs = hm + 128;

    const int tid  = threadIdx.x;
    const int lane = tid & 31;
    const int warp = tid >> 5;
    const int wq   = warp >> 1;
    const int wk   = warp & 1;
    const int lr   = lane >> 2;
    const int lc   = lane & 3;
    const int b = blockIdx.z, h = blockIdx.y;
    const int q0 = blockIdx.x * 64;

    const unsigned smbase = (unsigned)__cvta_generic_to_shared(sm32);
    const unsigned KSOFF = 64u*SRH*4u;
    const unsigned VSOFF = 2u*64u*SRH*4u;
    const unsigned PSOFF = 3u*64u*SRH*4u;

    // ldmatrix addresses (constant across kc loop; +32B per t-step)
    const int mi  = lane >> 3;
    const int mi0 = mi & 1, mi1 = mi >> 1;
    const int rw  = lane & 7;
    unsigned qad, pad, kad[2], vad[2];
    {
        int rowA = 16*wq + mi0*8 + rw;
        qad = smbase + (unsigned)(rowA*SRH + 4*mi1) * 4u;
        pad = smbase + PSOFF + (unsigned)(rowA*SRH + 4*mi1) * 4u;
        #pragma unroll
        for (int g = 0; g < 2; g++) {
            int rowB = 32*wk + (2*g + mi1)*8 + rw;
            kad[g] = smbase + KSOFF + (unsigned)(rowB*SRH + 4*mi0) * 4u;
            vad[g] = smbase + VSOFF + (unsigned)(rowB*SRH + 4*mi0) * 4u;
        }
    }

    {
        const __half2 sc = __float2half2_rn(0.125f);
        int r  = tid >> 2;
        int j0 = tid & 3;
        const uint2* src = (const uint2*)(QH + (size_t)(b*NQ + q0 + r)*CC + h*HD);
        #pragma unroll
        for (int i = 0; i < 4; i++) {
            int j = j0 + 4*i;
            uint2 v = src[j];
            __half2 h0 = __hmul2(*(__half2*)&v.x, sc);
            __half2 h1 = __hmul2(*(__half2*)&v.y, sc);
            Qs[r*SRH + 2*j]     = *(uint32_t*)&h0;
            Qs[r*SRH + 2*j + 1] = *(uint32_t*)&h1;
        }
    }

    const int row0 = 16*wq + lr;
    const int row1 = row0 + 8;

    float m0 = -1e30f, m1 = -1e30f, l0 = 0.f, l1 = 0.f;
    float oacc[4][4];
    #pragma unroll
    for (int fn = 0; fn < 4; fn++)
        #pragma unroll
        for (int r = 0; r < 4; r++) oacc[fn][r] = 0.f;

    for (int kc = 0; kc < NC; kc += 64) {
        __syncthreads();

        {
            int r  = tid >> 2;
            int j0 = tid & 3;
            const uint2* srcK = (const uint2*)(KV + (size_t)(b*NC + kc + r)*(2*CC) + h*HD);
            const uint2* srcV = (const uint2*)(KV + (size_t)(b*NC + kc + r)*(2*CC) + CC + h*HD);
            __half* Vh = (__half*)Vs;
            #pragma unroll
            for (int i = 0; i < 4; i++) {
                int j = j0 + 4*i;
                uint2 kv = srcK[j];
                Ks[r*SRH + 2*j]     = kv.x;
                Ks[r*SRH + 2*j + 1] = kv.y;
                uint2 vv = srcV[j];
                __half2 v0 = *(__half2*)&vv.x;
                __half2 v1 = *(__half2*)&vv.y;
                int d0 = 4*j;
                Vh[(d0 + 0)*(2*SRH) + r] = __low2half(v0);
                Vh[(d0 + 1)*(2*SRH) + r] = __high2half(v0);
                Vh[(d0 + 2)*(2*SRH) + r] = __low2half(v1);
                Vh[(d0 + 3)*(2*SRH) + r] = __high2half(v1);
            }
            if (tid < 64)
                Mv[tid] = (mask[b*NC + kc + tid] != 0) ? 0.f : -1e30f;
        }
        __syncthreads();

        // ---- S = Q @ K^T ----
        float sfr[4][4];
        #pragma unroll
        for (int fn = 0; fn < 4; fn++)
            #pragma unroll
            for (int r = 0; r < 4; r++) sfr[fn][r] = 0.f;

        #pragma unroll
        for (int t = 0; t < 4; t++) {
            uint32_t af[4], bf[2][4];
            ldsm_x4(af,    qad    + t*32u);
            ldsm_x4(bf[0], kad[0] + t*32u);
            ldsm_x4(bf[1], kad[1] + t*32u);
            #pragma unroll
            for (int fn = 0; fn < 4; fn++)
                MMA_F16(sfr[fn], af[0], af[1], af[2], af[3],
                        bf[fn >> 1][(fn & 1) * 2], bf[fn >> 1][(fn & 1) * 2 + 1]);
        }

        float mx0 = -1e30f, mx1 = -1e30f;
        float mc0[4], mc1[4];
        #pragma unroll
        for (int fn = 0; fn < 4; fn++) {
            int col = 32*wk + 8*fn + 2*lc;
            mc0[fn] = Mv[col];
            mc1[fn] = Mv[col + 1];
            sfr[fn][0] += mc0[fn]; sfr[fn][1] += mc1[fn];
            sfr[fn][2] += mc0[fn]; sfr[fn][3] += mc1[fn];
            mx0 = fmaxf(mx0, fmaxf(sfr[fn][0], sfr[fn][1]));
            mx1 = fmaxf(mx1, fmaxf(sfr[fn][2], sfr[fn][3]));
        }
        mx0 = fmaxf(mx0, __shfl_xor_sync(0xffffffffu, mx0, 1));
        mx0 = fmaxf(mx0, __shfl_xor_sync(0xffffffffu, mx0, 2));
        mx1 = fmaxf(mx1, __shfl_xor_sync(0xffffffffu, mx1, 1));
        mx1 = fmaxf(mx1, __shfl_xor_sync(0xffffffffu, mx1, 2));
        if (lc == 0) {
            hm[wk*64 + row0] = mx0;
            hm[wk*64 + row1] = mx1;
        }
        __syncthreads();

        const float nm0 = fmaxf(m0, fmaxf(hm[row0], hm[64 + row0]));
        const float nm1 = fmaxf(m1, fmaxf(hm[row1], hm[64 + row1]));
        const float al0 = __expf(m0 - nm0);
        const float al1 = __expf(m1 - nm1);

        float sum0 = 0.f, sum1 = 0.f;
        #pragma unroll
        for (int fn = 0; fn < 4; fn++) {
            float mb0 = (mc0[fn] == 0.f) ? 1.f : 0.f;
            float mb1 = (mc1[fn] == 0.f) ? 1.f : 0.f;
            float p0 = __expf(sfr[fn][0] - nm0) * mb0;
            float p1 = __expf(sfr[fn][1] - nm0) * mb1;
            float p2 = __expf(sfr[fn][2] - nm1) * mb0;
            float p3 = __expf(sfr[fn][3] - nm1) * mb1;
            sum0 += p0 + p1;
            sum1 += p2 + p3;
            int ui = 16*wk + 4*fn + lc;
            __half2 hp0 = __floats2half2_rn(p0, p1);
            __half2 hp1 = __floats2half2_rn(p2, p3);
            Ps[row0*SRH + ui] = *(uint32_t*)&hp0;
            Ps[row1*SRH + ui] = *(uint32_t*)&hp1;
        }
        sum0 += __shfl_xor_sync(0xffffffffu, sum0, 1);
        sum0 += __shfl_xor_sync(0xffffffffu, sum0, 2);
        sum1 += __shfl_xor_sync(0xffffffffu, sum1, 1);
        sum1 += __shfl_xor_sync(0xffffffffu, sum1, 2);
        if (lc == 0) {
            hs[wk*64 + row0] = sum0;
            hs[wk*64 + row1] = sum1;
        }

        #pragma unroll
        for (int fn = 0; fn < 4; fn++) {
            oacc[fn][0] *= al0; oacc[fn][1] *= al0;
            oacc[fn][2] *= al1; oacc[fn][3] *= al1;
        }
        __syncthreads();

        l0 = l0 * al0 + hs[row0] + hs[64 + row0];
        l1 = l1 * al1 + hs[row1] + hs[64 + row1];
        m0 = nm0; m1 = nm1;

        // ---- O += P @ V ----
        #pragma unroll
        for (int t = 0; t < 4; t++) {
            uint32_t af[4], bf[2][4];
            ldsm_x4(af,    pad    + t*32u);
            ldsm_x4(bf[0], vad[0] + t*32u);
            ldsm_x4(bf[1], vad[1] + t*32u);
            #pragma unroll
            for (int fn = 0; fn < 4; fn++)
                MMA_F16(oacc[fn], af[0], af[1], af[2], af[3],
                        bf[fn >> 1][(fn & 1) * 2], bf[fn >> 1][(fn & 1) * 2 + 1]);
        }
    }

    const float il0 = 1.f / l0;
    const float il1 = 1.f / l1;
    #pragma unroll
    for (int fn = 0; fn < 4; fn++) {
        int col = h*HD + 32*wk + 8*fn + 2*lc;
        *(__half2*)(OUT + (size_t)(b*NQ + q0 + row0)*CC + col) =
            __floats2half2_rn(oacc[fn][0]*il0, oacc[fn][1]*il0);
        *(__half2*)(OUT + (size_t)(b*NQ + q0 + row1)*CC + col) =
            __floats2half2_rn(oacc[fn][2]*il1, oacc[fn][3]*il1);
    }
}

// ---------------- orchestration ----------------
extern "C" void kernel_launch(void* const* d_in, const int* in_sizes, int n_in,
                              void* d_out, int out_size)
{
    const float* query   = (const float*)d_in[0];
    const float* context = (const float*)d_in[1];
    const int*   cmask   = (const int*)  d_in[2];
    const float* Wqp   = (const float*)d_in[3];
    const float* bqp   = (const float*)d_in[4];
    const float* Wcp   = (const float*)d_in[5];
    const float* bcp   = (const float*)d_in[6];
    const float* Wq    = (const float*)d_in[7];
    const float* bq    = (const float*)d_in[8];
    const float* Wkv   = (const float*)d_in[9];
    const float* bkv   = (const float*)d_in[10];
    const float* Wo    = (const float*)d_in[11];
    const float* bo    = (const float*)d_in[12];
    const float* g1    = (const float*)d_in[13];
    const float* beta1 = (const float*)d_in[14];
    const float* W1    = (const float*)d_in[15];
    const float* bf1   = (const float*)d_in[16];
    const float* W2    = (const float*)d_in[17];
    const float* bf2   = (const float*)d_in[18];
    const float* g2    = (const float*)d_in[19];
    const float* beta2 = (const float*)d_in[20];
    const float* gf    = (const float*)d_in[21];
    const float* betaf = (const float*)d_in[22];
    float* out = (float*)d_out;

    float  *bufQ;
    __half *bufC, *bufQN, *bufQH, *bufKV, *bufO, *bufF;
    __half *rQuery, *rCtx, *rWqp, *rWcp, *rWq, *rWkv, *rWo, *rW1, *rW2;
    cudaGetSymbolAddress((void**)&bufQ,  g_bufQ);
    cudaGetSymbolAddress((void**)&bufC,  g_bufC);
    cudaGetSymbolAddress((void**)&bufQN, g_bufQN);
    cudaGetSymbolAddress((void**)&bufQH, g_bufQH);
    cudaGetSymbolAddress((void**)&bufKV, g_bufKV);
    cudaGetSymbolAddress((void**)&bufO,  g_bufO);
    cudaGetSymbolAddress((void**)&bufF,  g_bufF);
    cudaGetSymbolAddress((void**)&rQuery, g_rQuery);
    cudaGetSymbolAddress((void**)&rCtx,   g_rCtx);
    cudaGetSymbolAddress((void**)&rWqp,   g_rWqp);
    cudaGetSymbolAddress((void**)&rWcp,   g_rWcp);
    cudaGetSymbolAddress((void**)&rWq,    g_rWq);
    cudaGetSymbolAddress((void**)&rWkv,   g_rWkv);
    cudaGetSymbolAddress((void**)&rWo,    g_rWo);
    cudaGetSymbolAddress((void**)&rW1,    g_rW1);
    cudaGetSymbolAddress((void**)&rW2,    g_rW2);

    const int smem_gemm = 4 * 16384;
    cudaFuncSetAttribute(gemm_f16,      cudaFuncAttributeMaxDynamicSharedMemorySize, smem_gemm);
    cudaFuncSetAttribute(gemm_f16_dual, cudaFuncAttributeMaxDynamicSharedMemorySize, smem_gemm);
    const int smem_attn = (4*64*SRH + 64 + 128 + 128) * 4;
    cudaFuncSetAttribute(attn_f16, cudaFuncAttributeMaxDynamicSharedMemorySize, smem_attn);

    const dim3 blk(256);
    const int MQ = B_ * NQ;   // 2048
    const int MC = B_ * NC;   // 8192

    // ---- prep ----
    tohalf<<<(B_*NQ*DQ)/1024, 256>>>(query,   rQuery, B_*NQ*DQ);
    tohalf<<<(B_*NC*DC)/1024, 256>>>(context, rCtx,   B_*NC*DC);
    {
        TTtab tab; int off = 0, i = 0;
        auto add = [&](const float* s, __half* d, int K, int N) {
            tab.p[i] = TTp{s, d, K, N, off};
            off += (N/32) * (K/32); i++;
        };
        add(Wqp, rWqp, DQ, CC);
        add(Wcp, rWcp, DC, CC);
        for (int l = 0; l < LL; l++) {
            add(Wq  + (size_t)l*CC*CC,   rWq  + (size_t)l*CC*CC,   CC, CC);
            add(Wkv + (size_t)l*CC*2*CC, rWkv + (size_t)l*CC*2*CC, CC, 2*CC);
            add(Wo  + (size_t)l*CC*CC,   rWo  + (size_t)l*CC*CC,   CC, CC);
            add(W1  + (size_t)l*CC*FF,   rW1  + (size_t)l*CC*FF,   CC, FF);
        }
        transpose_mega<<<off, dim3(32, 8)>>>(tab);
    }
    {
        TTtab tab; int off = 0, i = 0;
        for (int l = 0; l < LL; l++) {
            tab.p[i] = TTp{W2 + (size_t)l*FF*CC, rW2 + (size_t)l*FF*CC, FF, CC, off};
            off += (CC/32) * (FF/32); i++;
        }
        for (; i < MAXTT; i++) tab.p[i] = tab.p[i-1];
        transpose_mega<<<off, dim3(32, 8)>>>(tab);
    }

    // ---- input projections ----
    gemm_f16<<<dim3(CC/128, MQ/128), blk, smem_gemm>>>(rQuery, rWqp, bqp, nullptr, bufQ, CC, DQ, 0);
    gemm_f16<<<dim3(CC/128, MC/128), blk, smem_gemm>>>(rCtx,   rWcp, bcp, nullptr, bufC, CC, DC, 2);

    for (int l = 0; l < LL; l++) {
        ln_kernel<<<MQ, 256>>>(bufQ, g1 + l*CC, beta1 + l*CC, bufQN, 1);

        {
            GProb pkv { bufC,  rWkv + (size_t)l*CC*2*CC, bkv + l*2*CC, nullptr, bufKV, 2*CC, CC, 2*CC/128, 2 };
            GProb pq  { bufQN, rWq  + (size_t)l*CC*CC,   bq  + l*CC,   nullptr, bufQH, CC,   CC, CC/128,   2 };
            int nblk0 = (2*CC/128) * (MC/128);   // 1024
            int nblk1 = (CC/128) * (MQ/128);     // 128
            gemm_f16_dual<<<nblk0 + nblk1, blk, smem_gemm>>>(pkv, pq, nblk0);
        }

        attn_f16<<<dim3(NQ/64, HH, B_), blk, smem_attn>>>(bufQH, bufKV, cmask, bufO);

        gemm_f16<<<dim3(CC/128, MQ/128), blk, smem_gemm>>>(bufO, rWo + (size_t)l*CC*CC, bo + l*CC, bufQ, bufQ, CC, CC, 0);

        ln_kernel<<<MQ, 256>>>(bufQ, g2 + l*CC, beta2 + l*CC, bufQN, 1);

        gemm_f16<<<dim3(FF/128, MQ/128), blk, smem_gemm>>>(bufQN, rW1 + (size_t)l*CC*FF, bf1 + l*FF, nullptr, bufF, FF, CC, 3);
        gemm_f16<<<dim3(CC/128, MQ/128), blk, smem_gemm>>>(bufF,  rW2 + (size_t)l*FF*CC, bf2 + l*CC, bufQ,   bufQ, CC, FF, 0);
    }
    ln_kernel<<<MQ, 256>>>(bufQ, gf, betaf, out, 0);
}

// round 13
// speedup vs baseline: 1.8090x; 1.0969x over previous
#include <cuda_runtime.h>
#include <cuda_fp16.h>
#include <math.h>
#include <stdint.h>

#define B_  4
#define NQ  512
#define NC  2048
#define DQ  1024
#define DC  768
#define CC  1024
#define HH  16
#define HD  64
#define LL  2
#define FF  4096
#define EPSLN 1e-5f

// ---------------- scratch ----------------
__device__ float  g_bufQ [B_*NQ*CC];        // residual stream (fp32)
__device__ __half g_bufC [B_*NC*CC];
__device__ __half g_bufQN[B_*NQ*CC];
__device__ __half g_bufQH[B_*NQ*CC];
__device__ __half g_bufKV[B_*NC*2*CC];
__device__ __half g_bufO [B_*NQ*CC];
__device__ __half g_bufF [B_*NQ*FF];
__device__ __half g_rQuery[B_*NQ*DQ];
__device__ __half g_rCtx  [B_*NC*DC];
__device__ __half g_rWqp  [DQ*CC];
__device__ __half g_rWcp  [DC*CC];
__device__ __half g_rWq   [LL*CC*CC];
__device__ __half g_rWkv  [LL*CC*2*CC];
__device__ __half g_rWo   [LL*CC*CC];
__device__ __half g_rW1   [LL*CC*FF];
__device__ __half g_rW2   [LL*FF*CC];

#define MMA_F16(D, a0,a1,a2,a3, b0,b1)                                           \
    asm volatile(                                                                \
        "mma.sync.aligned.m16n8k16.row.col.f32.f16.f16.f32 "                     \
        "{%0,%1,%2,%3}, {%4,%5,%6,%7}, {%8,%9}, {%0,%1,%2,%3};\n"                \
        : "+f"((D)[0]), "+f"((D)[1]), "+f"((D)[2]), "+f"((D)[3])                 \
        : "r"(a0), "r"(a1), "r"(a2), "r"(a3), "r"(b0), "r"(b1))

__device__ __forceinline__ void ldsm_x4(uint32_t* r, unsigned addr) {
    asm volatile("ldmatrix.sync.aligned.m8n8.x4.shared.b16 {%0,%1,%2,%3}, [%4];"
        : "=r"(r[0]), "=r"(r[1]), "=r"(r[2]), "=r"(r[3]) : "r"(addr));
}
__device__ __forceinline__ void ldsm_x4t(uint32_t* r, unsigned addr) {
    asm volatile("ldmatrix.sync.aligned.m8n8.x4.trans.shared.b16 {%0,%1,%2,%3}, [%4];"
        : "=r"(r[0]), "=r"(r[1]), "=r"(r[2]), "=r"(r[3]) : "r"(addr));
}

__device__ __forceinline__ void cp16(unsigned dst, const void* src) {
    asm volatile("cp.async.cg.shared.global [%0], [%1], 16;" :: "r"(dst), "l"(src));
}
__device__ __forceinline__ void cpcommit() { asm volatile("cp.async.commit_group;"); }
__device__ __forceinline__ void cpwait0()  { asm volatile("cp.async.wait_group 0;"); }
__device__ __forceinline__ void cpwait1()  { asm volatile("cp.async.wait_group 1;"); }

// ---------------- prep ----------------
__global__ __launch_bounds__(256) void tohalf(
    const float* __restrict__ src, __half* __restrict__ dst, int n)
{
    int i = (blockIdx.x * 256 + threadIdx.x) * 4;
    if (i < n) {
        float4 v = *(const float4*)(src + i);
        __half2* d = (__half2*)(dst + i);
        d[0] = __floats2half2_rn(v.x, v.y);
        d[1] = __floats2half2_rn(v.z, v.w);
    }
}

#define MAXTT 10
struct TTp { const float* s; __half* d; int K; int N; int blk0; };
struct TTtab { TTp p[MAXTT]; };

__global__ void transpose_mega(TTtab tab)
{
    __shared__ float t[32][33];
    int b = blockIdx.x;
    int i = 0;
    #pragma unroll
    for (int j = 1; j < MAXTT; j++)
        if (b >= tab.p[j].blk0) i = j;
    const TTp P = tab.p[i];
    int lid = b - P.blk0;
    int nb  = P.N >> 5;
    const int n0 = (lid % nb) * 32, k0 = (lid / nb) * 32;
    const int tx = threadIdx.x, ty = threadIdx.y;
    #pragma unroll
    for (int q = 0; q < 4; q++)
        t[ty + 8*q][tx] = P.s[(size_t)(k0 + ty + 8*q) * P.N + n0 + tx];
    __syncthreads();
    #pragma unroll
    for (int q = 0; q < 4; q++)
        P.d[(size_t)(n0 + ty + 8*q) * P.K + k0 + tx] = __float2half(t[tx][ty + 8*q]);
}

// ---------------- fp16 GEMM body: BK=64 (128B rows), 3-stage cp.async, ldmatrix ----------------
// flags: 1=gelu, 2=half out
__device__ __forceinline__ void gemm_body(
    int bm, int bn, const __half* __restrict__ A,
    const __half* __restrict__ Bt, int K,
    const float* __restrict__ bias, const float* __restrict__ resid,
    void* __restrict__ outv, int N, int flags)
{
    extern __shared__ uint32_t smu[];   // 3 stages x 32KB: [A 16K | B 16K]
    const int tid  = threadIdx.x;
    const int lane = tid & 31;
    const int warp = tid >> 5;
    const int wmi  = warp >> 2;
    const int wni  = warp & 3;
    const int lr   = lane >> 2;
    const int lc   = lane & 3;

    // staging: row 0..127 (128B = 8 chunks of 16B), 2 threads/row, 4 chunks each
    const int srow = tid >> 1;
    const int c0s  = (tid & 1) * 4;
    const unsigned sbase = (unsigned)__cvta_generic_to_shared(smu);
    unsigned adst[4], bdst[4];
    #pragma unroll
    for (int i = 0; i < 4; i++) {
        int c = c0s + i;
        unsigned off = (unsigned)(srow*128 + ((c ^ (srow & 7)) * 16));
        adst[i] = sbase + off;
        bdst[i] = sbase + 16384u + off;
    }
    const __half* aSrc = A  + (size_t)(bm + srow) * K + 8*c0s;
    const __half* bSrc = Bt + (size_t)(bn + srow) * K + 8*c0s;

    // ldmatrix fragment addresses
    const int mi  = lane >> 3;
    const int mi0 = mi & 1, mi1 = mi >> 1;
    const int rw  = lane & 7;
    unsigned abase[4], bbase[2], aoff[4], boff[4];
    #pragma unroll
    for (int fm = 0; fm < 4; fm++)
        abase[fm] = sbase + (unsigned)((wmi*64 + fm*16 + mi0*8 + rw) * 128);
    #pragma unroll
    for (int g = 0; g < 2; g++)
        bbase[g] = sbase + 16384u + (unsigned)((wni*32 + (2*g + mi1)*8 + rw) * 128);
    #pragma unroll
    for (int t16 = 0; t16 < 4; t16++) {
        aoff[t16] = (unsigned)((((t16 << 1) | mi1) ^ rw) * 16);
        boff[t16] = (unsigned)((((t16 << 1) | mi0) ^ rw) * 16);
    }

    float acc[4][4][4];
    #pragma unroll
    for (int i = 0; i < 4; i++)
        #pragma unroll
        for (int j = 0; j < 4; j++)
            #pragma unroll
            for (int k = 0; k < 4; k++) acc[i][j][k] = 0.f;

    const int T = K >> 6;

    #define STAGE(t) do {                                                        \
        const unsigned boff_ = ((t) % 3) * 32768u;                               \
        const __half* sa = aSrc + (t) * 64;                                      \
        const __half* sb = bSrc + (t) * 64;                                      \
        _Pragma("unroll")                                                        \
        for (int i = 0; i < 4; i++) {                                            \
            cp16(adst[i] + boff_, sa + 8*i);                                     \
            cp16(bdst[i] + boff_, sb + 8*i);                                     \
        }                                                                        \
        cpcommit();                                                              \
    } while (0)

    STAGE(0); STAGE(1);

    for (int t = 0; t < T; t++) {
        if (t + 1 < T) cpwait1(); else cpwait0();
        __syncthreads();
        if (t + 2 < T) STAGE(t + 2);

        const unsigned sb_ = (t % 3) * 32768u;

        #pragma unroll
        for (int t16 = 0; t16 < 4; t16++) {
            uint32_t af[4][4], bf[2][4];
            #pragma unroll
            for (int fm = 0; fm < 4; fm++) ldsm_x4(af[fm], abase[fm] + aoff[t16] + sb_);
            #pragma unroll
            for (int g = 0; g < 2; g++)  ldsm_x4(bf[g],  bbase[g] + boff[t16] + sb_);
            #pragma unroll
            for (int fm = 0; fm < 4; fm++)
                #pragma unroll
                for (int fn = 0; fn < 4; fn++)
                    MMA_F16(acc[fm][fn], af[fm][0], af[fm][1], af[fm][2], af[fm][3],
                            bf[fn >> 1][(fn & 1) * 2], bf[fn >> 1][(fn & 1) * 2 + 1]);
        }
    }
    #undef STAGE

    const int do_gelu  = flags & 1;
    const int half_out = flags & 2;
    #pragma unroll
    for (int fm = 0; fm < 4; fm++) {
        #pragma unroll
        for (int fn = 0; fn < 4; fn++) {
            int row = bm + wmi*64 + fm*16 + lr;
            int col = bn + wni*32 + fn*8 + 2*lc;
            float2 bv = *(const float2*)(bias + col);

            float v0 = acc[fm][fn][0] + bv.x;
            float v1 = acc[fm][fn][1] + bv.y;
            float v2 = acc[fm][fn][2] + bv.x;
            float v3 = acc[fm][fn][3] + bv.y;
            if (do_gelu) {
                v0 = 0.5f * v0 * (1.f + erff(v0 * 0.70710678118654752f));
                v1 = 0.5f * v1 * (1.f + erff(v1 * 0.70710678118654752f));
                v2 = 0.5f * v2 * (1.f + erff(v2 * 0.70710678118654752f));
                v3 = 0.5f * v3 * (1.f + erff(v3 * 0.70710678118654752f));
            }
            if (resid) {
                float2 r0 = *(const float2*)(resid + (size_t)row * N + col);
                float2 r1 = *(const float2*)(resid + (size_t)(row + 8) * N + col);
                v0 += r0.x; v1 += r0.y; v2 += r1.x; v3 += r1.y;
            }
            if (half_out) {
                __half* o = (__half*)outv;
                *(__half2*)(o + (size_t)row * N + col)       = __floats2half2_rn(v0, v1);
                *(__half2*)(o + (size_t)(row + 8) * N + col) = __floats2half2_rn(v2, v3);
            } else {
                float* o = (float*)outv;
                *(float2*)(o + (size_t)row * N + col)        = make_float2(v0, v1);
                *(float2*)(o + (size_t)(row + 8) * N + col)  = make_float2(v2, v3);
            }
        }
    }
}

__global__ __launch_bounds__(256, 2) void gemm_f16(
    const __half* __restrict__ A, const __half* __restrict__ Bt,
    const float* __restrict__ bias, const float* __restrict__ resid,
    void* __restrict__ outv, int N, int K, int flags)
{
    gemm_body(blockIdx.y * 128, blockIdx.x * 128, A, Bt, K, bias, resid, outv, N, flags);
}

struct GProb { const __half* A; const __half* Bt; const float* bias;
               const float* resid; void* out; int N; int K; int gx; int flags; };
__global__ __launch_bounds__(256, 2) void gemm_f16_dual(GProb p0, GProb p1, int nblk0)
{
    int b = blockIdx.x;
    if (b < nblk0) {
        gemm_body((b / p0.gx) * 128, (b % p0.gx) * 128, p0.A, p0.Bt, p0.K,
                  p0.bias, p0.resid, p0.out, p0.N, p0.flags);
    } else {
        b -= nblk0;
        gemm_body((b / p1.gx) * 128, (b % p1.gx) * 128, p1.A, p1.Bt, p1.K,
                  p1.bias, p1.resid, p1.out, p1.N, p1.flags);
    }
}

// ---------------- LayerNorm ----------------
__global__ __launch_bounds__(256) void ln_kernel(
    const float* __restrict__ x, const float* __restrict__ g,
    const float* __restrict__ b, void* __restrict__ yv, int half_out)
{
    __shared__ float red[256];
    const int row = blockIdx.x;
    const int tid = threadIdx.x;
    const float* xr = x + (size_t)row * CC;

    float v[4];
    float s = 0.f;
    #pragma unroll
    for (int i = 0; i < 4; i++) { v[i] = xr[tid + i*256]; s += v[i]; }
    red[tid] = s; __syncthreads();
    for (int off = 128; off > 0; off >>= 1) {
        if (tid < off) red[tid] += red[tid + off];
        __syncthreads();
    }
    const float mean = red[0] * (1.f / CC);
    __syncthreads();

    float sq = 0.f;
    #pragma unroll
    for (int i = 0; i < 4; i++) { float d = v[i] - mean; sq += d * d; }
    red[tid] = sq; __syncthreads();
    for (int off = 128; off > 0; off >>= 1) {
        if (tid < off) red[tid] += red[tid + off];
        __syncthreads();
    }
    const float rstd = rsqrtf(red[0] * (1.f / CC) + EPSLN);

    #pragma unroll
    for (int i = 0; i < 4; i++) {
        int c = tid + i*256;
        float o = (v[i] - mean) * rstd * g[c] + b[c];
        if (half_out) ((__half*)yv)[(size_t)row * CC + c] = __float2half(o);
        else          ((float*)yv)[(size_t)row * CC + c] = o;
    }
}

// ---------------- fp16 flash attention: cp.async K/V double-buffer + ldmatrix.trans V ----------------
#define SRH 36                      // row stride in u32 (144 B)
#define KOFF(buf)  ((2304u + (buf)*2304u) * 4u)
#define VOFF(buf)  ((6912u + (buf)*2304u) * 4u)
#define PSOFF      (11520u * 4u)
#define MVOFF(buf) ((13824u + (buf)*64u) * 4u)
#define HMOFF      (13952u)
#define HSOFF      (14080u)
#define ATT_SMEM   (14208 * 4)

__global__ __launch_bounds__(256) void attn_f16(
    const __half* __restrict__ QH, const __half* __restrict__ KV,
    const int* __restrict__ mask, __half* __restrict__ OUT)
{
    extern __shared__ uint32_t sm32[];
    uint32_t* Qs = sm32;
    uint32_t* Ps = sm32 + 11520;
    float*    hm = (float*)(sm32 + HMOFF);
    float*    hs = (float*)(sm32 + HSOFF);

    const int tid  = threadIdx.x;
    const int lane = tid & 31;
    const int warp = tid >> 5;
    const int wq   = warp >> 1;
    const int wk   = warp & 1;
    const int lr   = lane >> 2;
    const int lc   = lane & 3;
    const int b = blockIdx.z, h = blockIdx.y;
    const int q0 = blockIdx.x * 64;

    const unsigned smbase = (unsigned)__cvta_generic_to_shared(sm32);

    // cp.async staging map: row = tid>>2 (0..63), 2 chunks per thread per tensor
    const int srow = tid >> 2;
    const int sc0  = (tid & 3) * 2;
    const unsigned kst0 = smbase + (unsigned)(srow*144 + sc0*16);
    const __half* kvRow = KV + (size_t)(b*NC + srow) * (2*CC) + h*HD + sc0*8;
    const int* mrow = mask + b*NC + 4*tid;   // tid<16 stages 64 ints

    #define ASTAGE(c) do {                                                       \
        const int buf_ = (c) & 1;                                                \
        const __half* sk = kvRow + (size_t)(c) * 64 * (2*CC);                    \
        cp16(kst0 + KOFF(buf_),       sk);                                       \
        cp16(kst0 + KOFF(buf_) + 16,  sk + 8);                                   \
        cp16(kst0 + VOFF(buf_),       sk + CC);                                  \
        cp16(kst0 + VOFF(buf_) + 16,  sk + CC + 8);                              \
        if (tid < 16)                                                            \
            cp16(smbase + MVOFF(buf_) + tid*16u, mrow + (c)*64);                 \
        cpcommit();                                                              \
    } while (0)

    // fragment addresses
    const int mi  = lane >> 3;
    const int mi0 = mi & 1, mi1 = mi >> 1;
    const int rw  = lane & 7;
    unsigned qad, pad, kad[2], vad[2];
    {
        int rowA = 16*wq + mi0*8 + rw;
        qad = smbase + (unsigned)(rowA*144 + mi1*16);
        pad = smbase + PSOFF + (unsigned)(rowA*144 + mi1*16);
        #pragma unroll
        for (int g = 0; g < 2; g++) {
            int rowB = 32*wk + (2*g + mi1)*8 + rw;        // K: [key][d]
            kad[g] = smbase + (unsigned)(rowB*144 + mi0*16);
            int rowV = mi0*8 + rw;                        // V: [key][d] + .trans
            int colV = 32*wk + (2*g + mi1)*8;
            vad[g] = smbase + (unsigned)(rowV*144 + colV*2);
        }
    }

    // stage Q (scaled by 0.125)
    {
        const __half2 sc = __float2half2_rn(0.125f);
        int r  = tid >> 2;
        int j0 = tid & 3;
        const uint2* src = (const uint2*)(QH + (size_t)(b*NQ + q0 + r)*CC + h*HD);
        #pragma unroll
        for (int i = 0; i < 4; i++) {
            int j = j0 + 4*i;
            uint2 v = src[j];
            __half2 h0 = __hmul2(*(__half2*)&v.x, sc);
            __half2 h1 = __hmul2(*(__half2*)&v.y, sc);
            Qs[r*SRH + 2*j]     = *(uint32_t*)&h0;
            Qs[r*SRH + 2*j + 1] = *(uint32_t*)&h1;
        }
    }

    const int row0 = 16*wq + lr;
    const int row1 = row0 + 8;

    float m0 = -1e30f, m1 = -1e30f, l0 = 0.f, l1 = 0.f;
    float oacc[4][4];
    #pragma unroll
    for (int fn = 0; fn < 4; fn++)
        #pragma unroll
        for (int r = 0; r < 4; r++) oacc[fn][r] = 0.f;

    ASTAGE(0);

    const int NCC = NC / 64;   // 32
    for (int c = 0; c < NCC; c++) {
        cpwait0();
        __syncthreads();            // K/V/mask(c) visible; prev chunk fully consumed
        if (c + 1 < NCC) ASTAGE(c + 1);

        const unsigned kb = KOFF(c & 1);
        const unsigned vb = VOFF(c & 1);
        const int* mv = (const int*)((const char*)sm32 + MVOFF(c & 1));

        // ---- S = Q @ K^T ----
        float sfr[4][4];
        #pragma unroll
        for (int fn = 0; fn < 4; fn++)
            #pragma unroll
            for (int r = 0; r < 4; r++) sfr[fn][r] = 0.f;

        #pragma unroll
        for (int t = 0; t < 4; t++) {
            uint32_t af[4], bf[2][4];
            ldsm_x4(af,    qad + t*32u);
            ldsm_x4(bf[0], kad[0] + kb + t*32u);
            ldsm_x4(bf[1], kad[1] + kb + t*32u);
            #pragma unroll
            for (int fn = 0; fn < 4; fn++)
                MMA_F16(sfr[fn], af[0], af[1], af[2], af[3],
                        bf[fn >> 1][(fn & 1) * 2], bf[fn >> 1][(fn & 1) * 2 + 1]);
        }

        float mx0 = -1e30f, mx1 = -1e30f;
        float mc0[4], mc1[4];
        #pragma unroll
        for (int fn = 0; fn < 4; fn++) {
            int col = 32*wk + 8*fn + 2*lc;
            mc0[fn] = mv[col]     ? 0.f : -1e30f;
            mc1[fn] = mv[col + 1] ? 0.f : -1e30f;
            sfr[fn][0] += mc0[fn]; sfr[fn][1] += mc1[fn];
            sfr[fn][2] += mc0[fn]; sfr[fn][3] += mc1[fn];
            mx0 = fmaxf(mx0, fmaxf(sfr[fn][0], sfr[fn][1]));
            mx1 = fmaxf(mx1, fmaxf(sfr[fn][2], sfr[fn][3]));
        }
        mx0 = fmaxf(mx0, __shfl_xor_sync(0xffffffffu, mx0, 1));
        mx0 = fmaxf(mx0, __shfl_xor_sync(0xffffffffu, mx0, 2));
        mx1 = fmaxf(mx1, __shfl_xor_sync(0xffffffffu, mx1, 1));
        mx1 = fmaxf(mx1, __shfl_xor_sync(0xffffffffu, mx1, 2));
        if (lc == 0) {
            hm[wk*64 + row0] = mx0;
            hm[wk*64 + row1] = mx1;
        }
        __syncthreads();

        const float nm0 = fmaxf(m0, fmaxf(hm[row0], hm[64 + row0]));
        const float nm1 = fmaxf(m1, fmaxf(hm[row1], hm[64 + row1]));
        const float al0 = __expf(m0 - nm0);
        const float al1 = __expf(m1 - nm1);

        float sum0 = 0.f, sum1 = 0.f;
        #pragma unroll
        for (int fn = 0; fn < 4; fn++) {
            float mb0 = (mc0[fn] == 0.f) ? 1.f : 0.f;
            float mb1 = (mc1[fn] == 0.f) ? 1.f : 0.f;
            float p0 = __expf(sfr[fn][0] - nm0) * mb0;
            float p1 = __expf(sfr[fn][1] - nm0) * mb1;
            float p2 = __expf(sfr[fn][2] - nm1) * mb0;
            float p3 = __expf(sfr[fn][3] - nm1) * mb1;
            sum0 += p0 + p1;
            sum1 += p2 + p3;
            int ui = 16*wk + 4*fn + lc;
            __half2 hp0 = __floats2half2_rn(p0, p1);
            __half2 hp1 = __floats2half2_rn(p2, p3);
            Ps[row0*SRH + ui] = *(uint32_t*)&hp0;
            Ps[row1*SRH + ui] = *(uint32_t*)&hp1;
        }
        sum0 += __shfl_xor_sync(0xffffffffu, sum0, 1);
        sum0 += __shfl_xor_sync(0xffffffffu, sum0, 2);
        sum1 += __shfl_xor_sync(0xffffffffu, sum1, 1);
        sum1 += __shfl_xor_sync(0xffffffffu, sum1, 2);
        if (lc == 0) {
            hs[wk*64 + row0] = sum0;
            hs[wk*64 + row1] = sum1;
        }

        #pragma unroll
        for (int fn = 0; fn < 4; fn++) {
            oacc[fn][0] *= al0; oacc[fn][1] *= al0;
            oacc[fn][2] *= al1; oacc[fn][3] *= al1;
        }
        __syncthreads();

        l0 = l0 * al0 + hs[row0] + hs[64 + row0];
        l1 = l1 * al1 + hs[row1] + hs[64 + row1];
        m0 = nm0; m1 = nm1;

        // ---- O += P @ V (V via ldmatrix.trans from [key][d]) ----
        #pragma unroll
        for (int t = 0; t < 4; t++) {
            uint32_t af[4], bf[2][4];
            ldsm_x4(af,     pad + t*32u);
            ldsm_x4t(bf[0], vad[0] + vb + t*2304u);
            ldsm_x4t(bf[1], vad[1] + vb + t*2304u);
            #pragma unroll
            for (int fn = 0; fn < 4; fn++)
                MMA_F16(oacc[fn], af[0], af[1], af[2], af[3],
                        bf[fn >> 1][(fn & 1) * 2], bf[fn >> 1][(fn & 1) * 2 + 1]);
        }
    }
    #undef ASTAGE

    const float il0 = 1.f / l0;
    const float il1 = 1.f / l1;
    #pragma unroll
    for (int fn = 0; fn < 4; fn++) {
        int col = h*HD + 32*wk + 8*fn + 2*lc;
        *(__half2*)(OUT + (size_t)(b*NQ + q0 + row0)*CC + col) =
            __floats2half2_rn(oacc[fn][0]*il0, oacc[fn][1]*il0);
        *(__half2*)(OUT + (size_t)(b*NQ + q0 + row1)*CC + col) =
            __floats2half2_rn(oacc[fn][2]*il1, oacc[fn][3]*il1);
    }
}

// ---------------- orchestration ----------------
extern "C" void kernel_launch(void* const* d_in, const int* in_sizes, int n_in,
                              void* d_out, int out_size)
{
    const float* query   = (const float*)d_in[0];
    const float* context = (const float*)d_in[1];
    const int*   cmask   = (const int*)  d_in[2];
    const float* Wqp   = (const float*)d_in[3];
    const float* bqp   = (const float*)d_in[4];
    const float* Wcp   = (const float*)d_in[5];
    const float* bcp   = (const float*)d_in[6];
    const float* Wq    = (const float*)d_in[7];
    const float* bq    = (const float*)d_in[8];
    const float* Wkv   = (const float*)d_in[9];
    const float* bkv   = (const float*)d_in[10];
    const float* Wo    = (const float*)d_in[11];
    const float* bo    = (const float*)d_in[12];
    const float* g1    = (const float*)d_in[13];
    const float* beta1 = (const float*)d_in[14];
    const float* W1    = (const float*)d_in[15];
    const float* bf1   = (const float*)d_in[16];
    const float* W2    = (const float*)d_in[17];
    const float* bf2   = (const float*)d_in[18];
    const float* g2    = (const float*)d_in[19];
    const float* beta2 = (const float*)d_in[20];
    const float* gf    = (const float*)d_in[21];
    const float* betaf = (const float*)d_in[22];
    float* out = (float*)d_out;

    float  *bufQ;
    __half *bufC, *bufQN, *bufQH, *bufKV, *bufO, *bufF;
    __half *rQuery, *rCtx, *rWqp, *rWcp, *rWq, *rWkv, *rWo, *rW1, *rW2;
    cudaGetSymbolAddress((void**)&bufQ,  g_bufQ);
    cudaGetSymbolAddress((void**)&bufC,  g_bufC);
    cudaGetSymbolAddress((void**)&bufQN, g_bufQN);
    cudaGetSymbolAddress((void**)&bufQH, g_bufQH);
    cudaGetSymbolAddress((void**)&bufKV, g_bufKV);
    cudaGetSymbolAddress((void**)&bufO,  g_bufO);
    cudaGetSymbolAddress((void**)&bufF,  g_bufF);
    cudaGetSymbolAddress((void**)&rQuery, g_rQuery);
    cudaGetSymbolAddress((void**)&rCtx,   g_rCtx);
    cudaGetSymbolAddress((void**)&rWqp,   g_rWqp);
    cudaGetSymbolAddress((void**)&rWcp,   g_rWcp);
    cudaGetSymbolAddress((void**)&rWq,    g_rWq);
    cudaGetSymbolAddress((void**)&rWkv,   g_rWkv);
    cudaGetSymbolAddress((void**)&rWo,    g_rWo);
    cudaGetSymbolAddress((void**)&rW1,    g_rW1);
    cudaGetSymbolAddress((void**)&rW2,    g_rW2);

    const int smem_gemm = 3 * 32768;   // 96 KB
    cudaFuncSetAttribute(gemm_f16,      cudaFuncAttributeMaxDynamicSharedMemorySize, smem_gemm);
    cudaFuncSetAttribute(gemm_f16_dual, cudaFuncAttributeMaxDynamicSharedMemorySize, smem_gemm);
    cudaFuncSetAttribute(attn_f16, cudaFuncAttributeMaxDynamicSharedMemorySize, ATT_SMEM);

    const dim3 blk(256);
    const int MQ = B_ * NQ;   // 2048
    const int MC = B_ * NC;   // 8192

    // ---- prep ----
    tohalf<<<(B_*NQ*DQ)/1024, 256>>>(query,   rQuery, B_*NQ*DQ);
    tohalf<<<(B_*NC*DC)/1024, 256>>>(context, rCtx,   B_*NC*DC);
    {
        TTtab tab; int off = 0, i = 0;
        auto add = [&](const float* s, __half* d, int K, int N) {
            tab.p[i] = TTp{s, d, K, N, off};
            off += (N/32) * (K/32); i++;
        };
        add(Wqp, rWqp, DQ, CC);
        add(Wcp, rWcp, DC, CC);
        for (int l = 0; l < LL; l++) {
            add(Wq  + (size_t)l*CC*CC,   rWq  + (size_t)l*CC*CC,   CC, CC);
            add(Wkv + (size_t)l*CC*2*CC, rWkv + (size_t)l*CC*2*CC, CC, 2*CC);
            add(Wo  + (size_t)l*CC*CC,   rWo  + (size_t)l*CC*CC,   CC, CC);
            add(W1  + (size_t)l*CC*FF,   rW1  + (size_t)l*CC*FF,   CC, FF);
        }
        transpose_mega<<<off, dim3(32, 8)>>>(tab);
    }
    {
        TTtab tab; int off = 0, i = 0;
        for (int l = 0; l < LL; l++) {
            tab.p[i] = TTp{W2 + (size_t)l*FF*CC, rW2 + (size_t)l*FF*CC, FF, CC, off};
            off += (CC/32) * (FF/32); i++;
        }
        for (; i < MAXTT; i++) tab.p[i] = tab.p[i-1];
        transpose_mega<<<off, dim3(32, 8)>>>(tab);
    }

    // ---- input projections ----
    gemm_f16<<<dim3(CC/128, MQ/128), blk, smem_gemm>>>(rQuery, rWqp, bqp, nullptr, bufQ, CC, DQ, 0);
    gemm_f16<<<dim3(CC/128, MC/128), blk, smem_gemm>>>(rCtx,   rWcp, bcp, nullptr, bufC, CC, DC, 2);

    for (int l = 0; l < LL; l++) {
        ln_kernel<<<MQ, 256>>>(bufQ, g1 + l*CC, beta1 + l*CC, bufQN, 1);

        {
            GProb pkv { bufC,  rWkv + (size_t)l*CC*2*CC, bkv + l*2*CC, nullptr, bufKV, 2*CC, CC, 2*CC/128, 2 };
            GProb pq  { bufQN, rWq  + (size_t)l*CC*CC,   bq  + l*CC,   nullptr, bufQH, CC,   CC, CC/128,   2 };
            int nblk0 = (2*CC/128) * (MC/128);   // 1024
            int nblk1 = (CC/128) * (MQ/128);     // 128
            gemm_f16_dual<<<nblk0 + nblk1, blk, smem_gemm>>>(pkv, pq, nblk0);
        }

        attn_f16<<<dim3(NQ/64, HH, B_), blk, ATT_SMEM>>>(bufQH, bufKV, cmask, bufO);

        gemm_f16<<<dim3(CC/128, MQ/128), blk, smem_gemm>>>(bufO, rWo + (size_t)l*CC*CC, bo + l*CC, bufQ, bufQ, CC, CC, 0);

        ln_kernel<<<MQ, 256>>>(bufQ, g2 + l*CC, beta2 + l*CC, bufQN, 1);

        gemm_f16<<<dim3(FF/128, MQ/128), blk, smem_gemm>>>(bufQN, rW1 + (size_t)l*CC*FF, bf1 + l*FF, nullptr, bufF, FF, CC, 3);
        gemm_f16<<<dim3(CC/128, MQ/128), blk, smem_gemm>>>(bufF,  rW2 + (size_t)l*FF*CC, bf2 + l*CC, bufQ,   bufQ, CC, FF, 0);
    }
    ln_kernel<<<MQ, 256>>>(bufQ, gf, betaf, out, 0);
}

// round 15
// speedup vs baseline: 1.9586x; 1.0827x over previous
#include <cuda_runtime.h>
#include <cuda_fp16.h>
#include <math.h>
#include <stdint.h>

#define B_  4
#define NQ  512
#define NC  2048
#define DQ  1024
#define DC  768
#define CC  1024
#define HH  16
#define HD  64
#define LL  2
#define FF  4096
#define EPSLN 1e-5f

// ---------------- scratch ----------------
__device__ float  g_bufQ [B_*NQ*CC];        // residual stream (fp32)
__device__ __half g_bufC [B_*NC*CC];
__device__ __half g_bufQN[B_*NQ*CC];
__device__ __half g_bufQH[B_*NQ*CC];
__device__ __half g_bufKV[B_*NC*2*CC];
__device__ __half g_bufO [B_*NQ*CC];
__device__ __half g_bufF [B_*NQ*FF];
__device__ __half g_rQuery[B_*NQ*DQ];
__device__ __half g_rCtx  [B_*NC*DC];
__device__ __half g_rWqp  [DQ*CC];
__device__ __half g_rWcp  [DC*CC];
__device__ __half g_rWq   [LL*CC*CC];
__device__ __half g_rWkv  [LL*CC*2*CC];
__device__ __half g_rWo   [LL*CC*CC];
__device__ __half g_rW1   [LL*CC*FF];
__device__ __half g_rW2   [LL*FF*CC];

#define MMA_F16(D, a0,a1,a2,a3, b0,b1)                                           \
    asm volatile(                                                                \
        "mma.sync.aligned.m16n8k16.row.col.f32.f16.f16.f32 "                     \
        "{%0,%1,%2,%3}, {%4,%5,%6,%7}, {%8,%9}, {%0,%1,%2,%3};\n"                \
        : "+f"((D)[0]), "+f"((D)[1]), "+f"((D)[2]), "+f"((D)[3])                 \
        : "r"(a0), "r"(a1), "r"(a2), "r"(a3), "r"(b0), "r"(b1))

__device__ __forceinline__ void ldsm_x4(uint32_t* r, unsigned addr) {
    asm volatile("ldmatrix.sync.aligned.m8n8.x4.shared.b16 {%0,%1,%2,%3}, [%4];"
        : "=r"(r[0]), "=r"(r[1]), "=r"(r[2]), "=r"(r[3]) : "r"(addr));
}
__device__ __forceinline__ void ldsm_x4t(uint32_t* r, unsigned addr) {
    asm volatile("ldmatrix.sync.aligned.m8n8.x4.trans.shared.b16 {%0,%1,%2,%3}, [%4];"
        : "=r"(r[0]), "=r"(r[1]), "=r"(r[2]), "=r"(r[3]) : "r"(addr));
}

__device__ __forceinline__ void cp16(unsigned dst, const void* src) {
    asm volatile("cp.async.cg.shared.global [%0], [%1], 16;" :: "r"(dst), "l"(src));
}
__device__ __forceinline__ void cpcommit() { asm volatile("cp.async.commit_group;"); }
__device__ __forceinline__ void cpwait0()  { asm volatile("cp.async.wait_group 0;"); }
__device__ __forceinline__ void cpwait1()  { asm volatile("cp.async.wait_group 1;"); }

// ---------------- prep ----------------
__global__ __launch_bounds__(256) void tohalf(
    const float* __restrict__ src, __half* __restrict__ dst, int n)
{
    int i = (blockIdx.x * 256 + threadIdx.x) * 4;
    if (i < n) {
        float4 v = *(const float4*)(src + i);
        __half2* d = (__half2*)(dst + i);
        d[0] = __floats2half2_rn(v.x, v.y);
        d[1] = __floats2half2_rn(v.z, v.w);
    }
}

#define MAXTT 10
struct TTp { const float* s; __half* d; int K; int N; int blk0; };
struct TTtab { TTp p[MAXTT]; };

__global__ void transpose_mega(TTtab tab)
{
    __shared__ float t[32][33];
    int b = blockIdx.x;
    int i = 0;
    #pragma unroll
    for (int j = 1; j < MAXTT; j++)
        if (b >= tab.p[j].blk0) i = j;
    const TTp P = tab.p[i];
    int lid = b - P.blk0;
    int nb  = P.N >> 5;
    const int n0 = (lid % nb) * 32, k0 = (lid / nb) * 32;
    const int tx = threadIdx.x, ty = threadIdx.y;
    #pragma unroll
    for (int q = 0; q < 4; q++)
        t[ty + 8*q][tx] = P.s[(size_t)(k0 + ty + 8*q) * P.N + n0 + tx];
    __syncthreads();
    #pragma unroll
    for (int q = 0; q < 4; q++)
        P.d[(size_t)(n0 + ty + 8*q) * P.K + k0 + tx] = __float2half(t[tx][ty + 8*q]);
}

// ---------------- fp16 GEMM body: BK=64 (128B rows), 3-stage cp.async, ldmatrix ----------------
// flags: 1=gelu, 2=half out
__device__ __forceinline__ void gemm_body(
    int bm, int bn, const __half* __restrict__ A,
    const __half* __restrict__ Bt, int K,
    const float* __restrict__ bias, const float* __restrict__ resid,
    void* __restrict__ outv, int N, int flags)
{
    extern __shared__ uint32_t smu[];   // 3 stages x 32KB: [A 16K | B 16K]
    const int tid  = threadIdx.x;
    const int lane = tid & 31;
    const int warp = tid >> 5;
    const int wmi  = warp >> 2;
    const int wni  = warp & 3;
    const int lr   = lane >> 2;
    const int lc   = lane & 3;

    const int srow = tid >> 1;
    const int c0s  = (tid & 1) * 4;
    const unsigned sbase = (unsigned)__cvta_generic_to_shared(smu);
    unsigned adst[4], bdst[4];
    #pragma unroll
    for (int i = 0; i < 4; i++) {
        int c = c0s + i;
        unsigned off = (unsigned)(srow*128 + ((c ^ (srow & 7)) * 16));
        adst[i] = sbase + off;
        bdst[i] = sbase + 16384u + off;
    }
    const __half* aSrc = A  + (size_t)(bm + srow) * K + 8*c0s;
    const __half* bSrc = Bt + (size_t)(bn + srow) * K + 8*c0s;

    const int mi  = lane >> 3;
    const int mi0 = mi & 1, mi1 = mi >> 1;
    const int rw  = lane & 7;
    unsigned abase[4], bbase[2], aoff[4], boff[4];
    #pragma unroll
    for (int fm = 0; fm < 4; fm++)
        abase[fm] = sbase + (unsigned)((wmi*64 + fm*16 + mi0*8 + rw) * 128);
    #pragma unroll
    for (int g = 0; g < 2; g++)
        bbase[g] = sbase + 16384u + (unsigned)((wni*32 + (2*g + mi1)*8 + rw) * 128);
    #pragma unroll
    for (int t16 = 0; t16 < 4; t16++) {
        aoff[t16] = (unsigned)((((t16 << 1) | mi1) ^ rw) * 16);
        boff[t16] = (unsigned)((((t16 << 1) | mi0) ^ rw) * 16);
    }

    float acc[4][4][4];
    #pragma unroll
    for (int i = 0; i < 4; i++)
        #pragma unroll
        for (int j = 0; j < 4; j++)
            #pragma unroll
            for (int k = 0; k < 4; k++) acc[i][j][k] = 0.f;

    const int T = K >> 6;

    #define STAGE(t) do {                                                        \
        const unsigned boff_ = ((t) % 3) * 32768u;                               \
        const __half* sa = aSrc + (t) * 64;                                      \
        const __half* sb = bSrc + (t) * 64;                                      \
        _Pragma("unroll")                                                        \
        for (int i = 0; i < 4; i++) {                                            \
            cp16(adst[i] + boff_, sa + 8*i);                                     \
            cp16(bdst[i] + boff_, sb + 8*i);                                     \
        }                                                                        \
        cpcommit();                                                              \
    } while (0)

    STAGE(0); STAGE(1);

    for (int t = 0; t < T; t++) {
        if (t + 1 < T) cpwait1(); else cpwait0();
        __syncthreads();
        if (t + 2 < T) STAGE(t + 2);

        const unsigned sb_ = (t % 3) * 32768u;

        #pragma unroll
        for (int t16 = 0; t16 < 4; t16++) {
            uint32_t af[4][4], bf[2][4];
            #pragma unroll
            for (int fm = 0; fm < 4; fm++) ldsm_x4(af[fm], abase[fm] + aoff[t16] + sb_);
            #pragma unroll
            for (int g = 0; g < 2; g++)  ldsm_x4(bf[g],  bbase[g] + boff[t16] + sb_);
            #pragma unroll
            for (int fm = 0; fm < 4; fm++)
                #pragma unroll
                for (int fn = 0; fn < 4; fn++)
                    MMA_F16(acc[fm][fn], af[fm][0], af[fm][1], af[fm][2], af[fm][3],
                            bf[fn >> 1][(fn & 1) * 2], bf[fn >> 1][(fn & 1) * 2 + 1]);
        }
    }
    #undef STAGE

    const int do_gelu  = flags & 1;
    const int half_out = flags & 2;
    #pragma unroll
    for (int fm = 0; fm < 4; fm++) {
        #pragma unroll
        for (int fn = 0; fn < 4; fn++) {
            int row = bm + wmi*64 + fm*16 + lr;
            int col = bn + wni*32 + fn*8 + 2*lc;
            float2 bv = *(const float2*)(bias + col);

            float v0 = acc[fm][fn][0] + bv.x;
            float v1 = acc[fm][fn][1] + bv.y;
            float v2 = acc[fm][fn][2] + bv.x;
            float v3 = acc[fm][fn][3] + bv.y;
            if (do_gelu) {
                v0 = 0.5f * v0 * (1.f + erff(v0 * 0.70710678118654752f));
                v1 = 0.5f * v1 * (1.f + erff(v1 * 0.70710678118654752f));
                v2 = 0.5f * v2 * (1.f + erff(v2 * 0.70710678118654752f));
                v3 = 0.5f * v3 * (1.f + erff(v3 * 0.70710678118654752f));
            }
            if (resid) {
                float2 r0 = *(const float2*)(resid + (size_t)row * N + col);
                float2 r1 = *(const float2*)(resid + (size_t)(row + 8) * N + col);
                v0 += r0.x; v1 += r0.y; v2 += r1.x; v3 += r1.y;
            }
            if (half_out) {
                __half* o = (__half*)outv;
                *(__half2*)(o + (size_t)row * N + col)       = __floats2half2_rn(v0, v1);
                *(__half2*)(o + (size_t)(row + 8) * N + col) = __floats2half2_rn(v2, v3);
            } else {
                float* o = (float*)outv;
                *(float2*)(o + (size_t)row * N + col)        = make_float2(v0, v1);
                *(float2*)(o + (size_t)(row + 8) * N + col)  = make_float2(v2, v3);
            }
        }
    }
}

__global__ __launch_bounds__(256, 2) void gemm_f16(
    const __half* __restrict__ A, const __half* __restrict__ Bt,
    const float* __restrict__ bias, const float* __restrict__ resid,
    void* __restrict__ outv, int N, int K, int flags)
{
    gemm_body(blockIdx.y * 128, blockIdx.x * 128, A, Bt, K, bias, resid, outv, N, flags);
}

struct GProb { const __half* A; const __half* Bt; const float* bias;
               const float* resid; void* out; int N; int K; int gx; int flags; };
__global__ __launch_bounds__(256, 2) void gemm_f16_dual(GProb p0, GProb p1, int nblk0)
{
    int b = blockIdx.x;
    if (b < nblk0) {
        gemm_body((b / p0.gx) * 128, (b % p0.gx) * 128, p0.A, p0.Bt, p0.K,
                  p0.bias, p0.resid, p0.out, p0.N, p0.flags);
    } else {
        b -= nblk0;
        gemm_body((b / p1.gx) * 128, (b % p1.gx) * 128, p1.A, p1.Bt, p1.K,
                  p1.bias, p1.resid, p1.out, p1.N, p1.flags);
    }
}

// ---------------- LayerNorm ----------------
__global__ __launch_bounds__(256) void ln_kernel(
    const float* __restrict__ x, const float* __restrict__ g,
    const float* __restrict__ b, void* __restrict__ yv, int half_out)
{
    __shared__ float red[256];
    const int row = blockIdx.x;
    const int tid = threadIdx.x;
    const float* xr = x + (size_t)row * CC;

    float v[4];
    float s = 0.f;
    #pragma unroll
    for (int i = 0; i < 4; i++) { v[i] = xr[tid + i*256]; s += v[i]; }
    red[tid] = s; __syncthreads();
    for (int off = 128; off > 0; off >>= 1) {
        if (tid < off) red[tid] += red[tid + off];
        __syncthreads();
    }
    const float mean = red[0] * (1.f / CC);
    __syncthreads();

    float sq = 0.f;
    #pragma unroll
    for (int i = 0; i < 4; i++) { float d = v[i] - mean; sq += d * d; }
    red[tid] = sq; __syncthreads();
    for (int off = 128; off > 0; off >>= 1) {
        if (tid < off) red[tid] += red[tid + off];
        __syncthreads();
    }
    const float rstd = rsqrtf(red[0] * (1.f / CC) + EPSLN);

    #pragma unroll
    for (int i = 0; i < 4; i++) {
        int c = tid + i*256;
        float o = (v[i] - mean) * rstd * g[c] + b[c];
        if (half_out) ((__half*)yv)[(size_t)row * CC + c] = __float2half(o);
        else          ((float*)yv)[(size_t)row * CC + c] = o;
    }
}

// ---------------- fp16 flash attention v2: 128 q-rows/block, warp-private rows ----------------
#define ASRH 36                       // row stride in u32 (144 B)
#define AK_U32(b) (4608u + (b)*2304u)
#define AV_U32(b) (9216u + (b)*2304u)
#define AM_U32(b) (13824u + (b)*64u)
#define ATT_SMEM  (13952 * 4)         // 55808 B

__global__ __launch_bounds__(256) void attn_f16(
    const __half* __restrict__ QH, const __half* __restrict__ KV,
    const int* __restrict__ mask, __half* __restrict__ OUT)
{
    extern __shared__ uint32_t sm32[];
    uint32_t* Qs = sm32;

    const int tid  = threadIdx.x;
    const int lane = tid & 31;
    const int warp = tid >> 5;        // 0..7 -> q rows 16*warp..
    const int lr   = lane >> 2;
    const int lc   = lane & 3;
    const int b = blockIdx.z, h = blockIdx.y;
    const int q0 = blockIdx.x * 128;

    const unsigned smbase = (unsigned)__cvta_generic_to_shared(sm32);

    // cp.async staging: row = tid>>2 (0..63), 2 chunks of 16B per tensor
    const int srow = tid >> 2;
    const int sc0  = (tid & 3) * 2;
    const unsigned kst0 = smbase + (unsigned)(srow*144 + sc0*16);
    const __half* kvRow = KV + (size_t)(b*NC + srow) * (2*CC) + h*HD + sc0*8;
    const int* mrow = mask + b*NC + 4*tid;

    #define ASTAGE(c) do {                                                       \
        const int buf_ = (c) & 1;                                                \
        const __half* sk = kvRow + (size_t)(c) * 64 * (2*CC);                    \
        cp16(kst0 + AK_U32(buf_)*4u,      sk);                                   \
        cp16(kst0 + AK_U32(buf_)*4u + 16, sk + 8);                               \
        cp16(kst0 + AV_U32(buf_)*4u,      sk + CC);                              \
        cp16(kst0 + AV_U32(buf_)*4u + 16, sk + CC + 8);                          \
        if (tid < 16)                                                            \
            cp16(smbase + AM_U32(buf_)*4u + tid*16u, mrow + (c)*64);             \
        cpcommit();                                                              \
    } while (0)

    // fragment addresses
    const int mi  = lane >> 3;
    const int mi0 = mi & 1, mi1 = mi >> 1;
    const int rw  = lane & 7;
    const unsigned qad = smbase + (unsigned)((16*warp + mi0*8 + rw)*144 + mi1*16);
    unsigned kad[4], vad[4];
    #pragma unroll
    for (int g = 0; g < 4; g++) {
        kad[g] = smbase + (unsigned)((16*g + mi1*8 + rw)*144 + mi0*16);    // K [key][d]
        vad[g] = smbase + (unsigned)((mi0*8 + rw)*144 + (16*g + mi1*8)*2); // V [key][d] + .trans
    }

    // stage Q once (scaled by 0.125): 128 rows, 2 threads/row, 8 uint2 each (full 64 halves)
    {
        const __half2 sc = __float2half2_rn(0.125f);
        int r  = tid >> 1;
        int j0 = (tid & 1) * 8;
        const uint2* src = (const uint2*)(QH + (size_t)(b*NQ + q0 + r)*CC + h*HD);
        #pragma unroll
        for (int i = 0; i < 8; i++) {
            int j = j0 + i;
            uint2 v = src[j];
            __half2 h0 = __hmul2(*(__half2*)&v.x, sc);
            __half2 h1 = __hmul2(*(__half2*)&v.y, sc);
            Qs[r*ASRH + 2*j]     = *(uint32_t*)&h0;
            Qs[r*ASRH + 2*j + 1] = *(uint32_t*)&h1;
        }
    }
    ASTAGE(0);
    __syncthreads();

    // Q a-fragments: load once, reuse for all chunks
    uint32_t qf[4][4];
    #pragma unroll
    for (int t = 0; t < 4; t++) ldsm_x4(qf[t], qad + t*32u);

    const int row0 = 16*warp + lr;
    const int row1 = row0 + 8;

    float m0 = -1e30f, m1 = -1e30f, l0 = 0.f, l1 = 0.f;
    float oacc[8][4];
    #pragma unroll
    for (int fn = 0; fn < 8; fn++)
        #pragma unroll
        for (int r = 0; r < 4; r++) oacc[fn][r] = 0.f;

    const int NCC = NC / 64;   // 32
    for (int c = 0; c < NCC; c++) {
        cpwait0();
        __syncthreads();
        if (c + 1 < NCC) ASTAGE(c + 1);

        const unsigned kb = AK_U32(c & 1) * 4u;
        const unsigned vb = AV_U32(c & 1) * 4u;
        const int* mv = (const int*)(sm32 + AM_U32(c & 1));

        // ---- S = Q @ K^T  (16 rows x 64 keys per warp) ----
        float sfr[8][4];
        #pragma unroll
        for (int fn = 0; fn < 8; fn++)
            #pragma unroll
            for (int r = 0; r < 4; r++) sfr[fn][r] = 0.f;

        #pragma unroll
        for (int t = 0; t < 4; t++) {
            uint32_t kf[4][4];
            #pragma unroll
            for (int g = 0; g < 4; g++) ldsm_x4(kf[g], kad[g] + kb + t*32u);
            #pragma unroll
            for (int fn = 0; fn < 8; fn++)
                MMA_F16(sfr[fn], qf[t][0], qf[t][1], qf[t][2], qf[t][3],
                        kf[fn >> 1][(fn & 1) * 2], kf[fn >> 1][(fn & 1) * 2 + 1]);
        }

        // ---- mask (additive; running max finite after chunk 0) + row max ----
        float mx0 = -1e30f, mx1 = -1e30f;
        #pragma unroll
        for (int fn = 0; fn < 8; fn++) {
            int col = 8*fn + 2*lc;
            float a0 = mv[col]     ? 0.f : -1e30f;
            float a1 = mv[col + 1] ? 0.f : -1e30f;
            sfr[fn][0] += a0; sfr[fn][1] += a1;
            sfr[fn][2] += a0; sfr[fn][3] += a1;
            mx0 = fmaxf(mx0, fmaxf(sfr[fn][0], sfr[fn][1]));
            mx1 = fmaxf(mx1, fmaxf(sfr[fn][2], sfr[fn][3]));
        }
        mx0 = fmaxf(mx0, __shfl_xor_sync(0xffffffffu, mx0, 1));
        mx0 = fmaxf(mx0, __shfl_xor_sync(0xffffffffu, mx0, 2));
        mx1 = fmaxf(mx1, __shfl_xor_sync(0xffffffffu, mx1, 1));
        mx1 = fmaxf(mx1, __shfl_xor_sync(0xffffffffu, mx1, 2));

        const float nm0 = fmaxf(m0, mx0);
        const float nm1 = fmaxf(m1, mx1);
        const float al0 = __expf(m0 - nm0);
        const float al1 = __expf(m1 - nm1);

        // ---- p = exp(s - nm): pack straight into a-fragments (no smem) ----
        float sum0 = 0.f, sum1 = 0.f;
        uint32_t pf[4][4];
        #pragma unroll
        for (int t = 0; t < 4; t++) {
            const int fa = 2*t, fb = 2*t + 1;
            float p0 = __expf(sfr[fa][0] - nm0), p1 = __expf(sfr[fa][1] - nm0);
            float p2 = __expf(sfr[fa][2] - nm1), p3 = __expf(sfr[fa][3] - nm1);
            float p4 = __expf(sfr[fb][0] - nm0), p5 = __expf(sfr[fb][1] - nm0);
            float p6 = __expf(sfr[fb][2] - nm1), p7 = __expf(sfr[fb][3] - nm1);
            sum0 += p0 + p1 + p4 + p5;
            sum1 += p2 + p3 + p6 + p7;
            __half2 h0 = __floats2half2_rn(p0, p1);
            __half2 h1 = __floats2half2_rn(p2, p3);
            __half2 h2 = __floats2half2_rn(p4, p5);
            __half2 h3 = __floats2half2_rn(p6, p7);
            pf[t][0] = *(uint32_t*)&h0;
            pf[t][1] = *(uint32_t*)&h1;
            pf[t][2] = *(uint32_t*)&h2;
            pf[t][3] = *(uint32_t*)&h3;
        }
        sum0 += __shfl_xor_sync(0xffffffffu, sum0, 1);
        sum0 += __shfl_xor_sync(0xffffffffu, sum0, 2);
        sum1 += __shfl_xor_sync(0xffffffffu, sum1, 1);
        sum1 += __shfl_xor_sync(0xffffffffu, sum1, 2);

        l0 = l0 * al0 + sum0;
        l1 = l1 * al1 + sum1;
        m0 = nm0; m1 = nm1;

        #pragma unroll
        for (int fn = 0; fn < 8; fn++) {
            oacc[fn][0] *= al0; oacc[fn][1] *= al0;
            oacc[fn][2] *= al1; oacc[fn][3] *= al1;
        }

        // ---- O += P @ V (V via ldmatrix.trans from [key][d]) ----
        #pragma unroll
        for (int t = 0; t < 4; t++) {
            uint32_t vf[4][4];
            #pragma unroll
            for (int g = 0; g < 4; g++) ldsm_x4t(vf[g], vad[g] + vb + t*2304u);
            #pragma unroll
            for (int fn = 0; fn < 8; fn++)
                MMA_F16(oacc[fn], pf[t][0], pf[t][1], pf[t][2], pf[t][3],
                        vf[fn >> 1][(fn & 1) * 2], vf[fn >> 1][(fn & 1) * 2 + 1]);
        }
    }
    #undef ASTAGE

    const float il0 = 1.f / l0;
    const float il1 = 1.f / l1;
    #pragma unroll
    for (int fn = 0; fn < 8; fn++) {
        int col = h*HD + 8*fn + 2*lc;
        *(__half2*)(OUT + (size_t)(b*NQ + q0 + row0)*CC + col) =
            __floats2half2_rn(oacc[fn][0]*il0, oacc[fn][1]*il0);
        *(__half2*)(OUT + (size_t)(b*NQ + q0 + row1)*CC + col) =
            __floats2half2_rn(oacc[fn][2]*il1, oacc[fn][3]*il1);
    }
}

// ---------------- orchestration ----------------
extern "C" void kernel_launch(void* const* d_in, const int* in_sizes, int n_in,
                              void* d_out, int out_size)
{
    const float* query   = (const float*)d_in[0];
    const float* context = (const float*)d_in[1];
    const int*   cmask   = (const int*)  d_in[2];
    const float* Wqp   = (const float*)d_in[3];
    const float* bqp   = (const float*)d_in[4];
    const float* Wcp   = (const float*)d_in[5];
    const float* bcp   = (const float*)d_in[6];
    const float* Wq    = (const float*)d_in[7];
    const float* bq    = (const float*)d_in[8];
    const float* Wkv   = (const float*)d_in[9];
    const float* bkv   = (const float*)d_in[10];
    const float* Wo    = (const float*)d_in[11];
    const float* bo    = (const float*)d_in[12];
    const float* g1    = (const float*)d_in[13];
    const float* beta1 = (const float*)d_in[14];
    const float* W1    = (const float*)d_in[15];
    const float* bf1   = (const float*)d_in[16];
    const float* W2    = (const float*)d_in[17];
    const float* bf2   = (const float*)d_in[18];
    const float* g2    = (const float*)d_in[19];
    const float* beta2 = (const float*)d_in[20];
    const float* gf    = (const float*)d_in[21];
    const float* betaf = (const float*)d_in[22];
    float* out = (float*)d_out;

    float  *bufQ;
    __half *bufC, *bufQN, *bufQH, *bufKV, *bufO, *bufF;
    __half *rQuery, *rCtx, *rWqp, *rWcp, *rWq, *rWkv, *rWo, *rW1, *rW2;
    cudaGetSymbolAddress((void**)&bufQ,  g_bufQ);
    cudaGetSymbolAddress((void**)&bufC,  g_bufC);
    cudaGetSymbolAddress((void**)&bufQN, g_bufQN);
    cudaGetSymbolAddress((void**)&bufQH, g_bufQH);
    cudaGetSymbolAddress((void**)&bufKV, g_bufKV);
    cudaGetSymbolAddress((void**)&bufO,  g_bufO);
    cudaGetSymbolAddress((void**)&bufF,  g_bufF);
    cudaGetSymbolAddress((void**)&rQuery, g_rQuery);
    cudaGetSymbolAddress((void**)&rCtx,   g_rCtx);
    cudaGetSymbolAddress((void**)&rWqp,   g_rWqp);
    cudaGetSymbolAddress((void**)&rWcp,   g_rWcp);
    cudaGetSymbolAddress((void**)&rWq,    g_rWq);
    cudaGetSymbolAddress((void**)&rWkv,   g_rWkv);
    cudaGetSymbolAddress((void**)&rWo,    g_rWo);
    cudaGetSymbolAddress((void**)&rW1,    g_rW1);
    cudaGetSymbolAddress((void**)&rW2,    g_rW2);

    const int smem_gemm = 3 * 32768;   // 96 KB
    cudaFuncSetAttribute(gemm_f16,      cudaFuncAttributeMaxDynamicSharedMemorySize, smem_gemm);
    cudaFuncSetAttribute(gemm_f16_dual, cudaFuncAttributeMaxDynamicSharedMemorySize, smem_gemm);
    cudaFuncSetAttribute(attn_f16, cudaFuncAttributeMaxDynamicSharedMemorySize, ATT_SMEM);

    const dim3 blk(256);
    const int MQ = B_ * NQ;   // 2048
    const int MC = B_ * NC;   // 8192

    // ---- prep ----
    tohalf<<<(B_*NQ*DQ)/1024, 256>>>(query,   rQuery, B_*NQ*DQ);
    tohalf<<<(B_*NC*DC)/1024, 256>>>(context, rCtx,   B_*NC*DC);
    {
        TTtab tab; int off = 0, i = 0;
        auto add = [&](const float* s, __half* d, int K, int N) {
            tab.p[i] = TTp{s, d, K, N, off};
            off += (N/32) * (K/32); i++;
        };
        add(Wqp, rWqp, DQ, CC);
        add(Wcp, rWcp, DC, CC);
        for (int l = 0; l < LL; l++) {
            add(Wq  + (size_t)l*CC*CC,   rWq  + (size_t)l*CC*CC,   CC, CC);
            add(Wkv + (size_t)l*CC*2*CC, rWkv + (size_t)l*CC*2*CC, CC, 2*CC);
            add(Wo  + (size_t)l*CC*CC,   rWo  + (size_t)l*CC*CC,   CC, CC);
            add(W1  + (size_t)l*CC*FF,   rW1  + (size_t)l*CC*FF,   CC, FF);
        }
        transpose_mega<<<off, dim3(32, 8)>>>(tab);
    }
    {
        TTtab tab; int off = 0, i = 0;
        for (int l = 0; l < LL; l++) {
            tab.p[i] = TTp{W2 + (size_t)l*FF*CC, rW2 + (size_t)l*FF*CC, FF, CC, off};
            off += (CC/32) * (FF/32); i++;
        }
        for (; i < MAXTT; i++) tab.p[i] = tab.p[i-1];
        transpose_mega<<<off, dim3(32, 8)>>>(tab);
    }

    // ---- input projections ----
    gemm_f16<<<dim3(CC/128, MQ/128), blk, smem_gemm>>>(rQuery, rWqp, bqp, nullptr, bufQ, CC, DQ, 0);
    gemm_f16<<<dim3(CC/128, MC/128), blk, smem_gemm>>>(rCtx,   rWcp, bcp, nullptr, bufC, CC, DC, 2);

    for (int l = 0; l < LL; l++) {
        ln_kernel<<<MQ, 256>>>(bufQ, g1 + l*CC, beta1 + l*CC, bufQN, 1);

        {
            GProb pkv { bufC,  rWkv + (size_t)l*CC*2*CC, bkv + l*2*CC, nullptr, bufKV, 2*CC, CC, 2*CC/128, 2 };
            GProb pq  { bufQN, rWq  + (size_t)l*CC*CC,   bq  + l*CC,   nullptr, bufQH, CC,   CC, CC/128,   2 };
            int nblk0 = (2*CC/128) * (MC/128);   // 1024
            int nblk1 = (CC/128) * (MQ/128);     // 128
            gemm_f16_dual<<<nblk0 + nblk1, blk, smem_gemm>>>(pkv, pq, nblk0);
        }

        attn_f16<<<dim3(NQ/128, HH, B_), blk, ATT_SMEM>>>(bufQH, bufKV, cmask, bufO);

        gemm_f16<<<dim3(CC/128, MQ/128), blk, smem_gemm>>>(bufO, rWo + (size_t)l*CC*CC, bo + l*CC, bufQ, bufQ, CC, CC, 0);

        ln_kernel<<<MQ, 256>>>(bufQ, g2 + l*CC, beta2 + l*CC, bufQN, 1);

        gemm_f16<<<dim3(FF/128, MQ/128), blk, smem_gemm>>>(bufQN, rW1 + (size_t)l*CC*FF, bf1 + l*FF, nullptr, bufF, FF, CC, 3);
        gemm_f16<<<dim3(CC/128, MQ/128), blk, smem_gemm>>>(bufF,  rW2 + (size_t)l*FF*CC, bf2 + l*CC, bufQ,   bufQ, CC, FF, 0);
    }
    ln_kernel<<<MQ, 256>>>(bufQ, gf, betaf, out, 0);
}

// round 17
// speedup vs baseline: 1.9833x; 1.0126x over previous
#include <cuda_runtime.h>
#include <cuda_fp16.h>
#include <math.h>
#include <stdint.h>

#define B_  4
#define NQ  512
#define NC  2048
#define DQ  1024
#define DC  768
#define CC  1024
#define HH  16
#define HD  64
#define LL  2
#define FF  4096
#define EPSLN 1e-5f

// ---------------- scratch ----------------
__device__ float  g_bufQ [B_*NQ*CC];        // residual stream (fp32)
__device__ __half g_bufC [B_*NC*CC];
__device__ __half g_bufQN[B_*NQ*CC];
__device__ __half g_bufQH[B_*NQ*CC];
__device__ __half g_bufKV [B_*NC*2*CC];     // layer 0 KV
__device__ __half g_bufKV2[B_*NC*2*CC];     // layer 1 KV
__device__ __half g_bufO [B_*NQ*CC];
__device__ __half g_bufF [B_*NQ*FF];
__device__ __half g_rQuery[B_*NQ*DQ];
__device__ __half g_rCtx  [B_*NC*DC];
__device__ __half g_rWqp  [DQ*CC];
__device__ __half g_rWcp  [DC*CC];
__device__ __half g_rWq   [LL*CC*CC];
__device__ __half g_rWkv  [LL*CC*2*CC];
__device__ __half g_rWo   [LL*CC*CC];
__device__ __half g_rW1   [LL*CC*FF];
__device__ __half g_rW2   [LL*FF*CC];

#define MMA_F16(D, a0,a1,a2,a3, b0,b1)                                           \
    asm volatile(                                                                \
        "mma.sync.aligned.m16n8k16.row.col.f32.f16.f16.f32 "                     \
        "{%0,%1,%2,%3}, {%4,%5,%6,%7}, {%8,%9}, {%0,%1,%2,%3};\n"                \
        : "+f"((D)[0]), "+f"((D)[1]), "+f"((D)[2]), "+f"((D)[3])                 \
        : "r"(a0), "r"(a1), "r"(a2), "r"(a3), "r"(b0), "r"(b1))

__device__ __forceinline__ void ldsm_x4(uint32_t* r, unsigned addr) {
    asm volatile("ldmatrix.sync.aligned.m8n8.x4.shared.b16 {%0,%1,%2,%3}, [%4];"
        : "=r"(r[0]), "=r"(r[1]), "=r"(r[2]), "=r"(r[3]) : "r"(addr));
}
__device__ __forceinline__ void ldsm_x4t(uint32_t* r, unsigned addr) {
    asm volatile("ldmatrix.sync.aligned.m8n8.x4.trans.shared.b16 {%0,%1,%2,%3}, [%4];"
        : "=r"(r[0]), "=r"(r[1]), "=r"(r[2]), "=r"(r[3]) : "r"(addr));
}

__device__ __forceinline__ void cp16(unsigned dst, const void* src) {
    asm volatile("cp.async.cg.shared.global [%0], [%1], 16;" :: "r"(dst), "l"(src));
}
__device__ __forceinline__ void cpcommit() { asm volatile("cp.async.commit_group;"); }
__device__ __forceinline__ void cpwait0()  { asm volatile("cp.async.wait_group 0;"); }
__device__ __forceinline__ void cpwait1()  { asm volatile("cp.async.wait_group 1;"); }

// ---------------- prep ----------------
__global__ __launch_bounds__(256) void tohalf(
    const float* __restrict__ src, __half* __restrict__ dst, int n)
{
    int i = (blockIdx.x * 256 + threadIdx.x) * 4;
    if (i < n) {
        float4 v = *(const float4*)(src + i);
        __half2* d = (__half2*)(dst + i);
        d[0] = __floats2half2_rn(v.x, v.y);
        d[1] = __floats2half2_rn(v.z, v.w);
    }
}

#define MAXTT 10
struct TTp { const float* s; __half* d; int K; int N; int blk0; };
struct TTtab { TTp p[MAXTT]; };

__global__ void transpose_mega(TTtab tab)
{
    __shared__ float t[32][33];
    int b = blockIdx.x;
    int i = 0;
    #pragma unroll
    for (int j = 1; j < MAXTT; j++)
        if (b >= tab.p[j].blk0) i = j;
    const TTp P = tab.p[i];
    int lid = b - P.blk0;
    int nb  = P.N >> 5;
    const int n0 = (lid % nb) * 32, k0 = (lid / nb) * 32;
    const int tx = threadIdx.x, ty = threadIdx.y;
    #pragma unroll
    for (int q = 0; q < 4; q++)
        t[ty + 8*q][tx] = P.s[(size_t)(k0 + ty + 8*q) * P.N + n0 + tx];
    __syncthreads();
    #pragma unroll
    for (int q = 0; q < 4; q++)
        P.d[(size_t)(n0 + ty + 8*q) * P.K + k0 + tx] = __float2half(t[tx][ty + 8*q]);
}

// ---------------- fp16 GEMM body: BK=64 (128B rows), 3-stage cp.async, ldmatrix ----------------
// flags: 1=gelu, 2=half out
__device__ __forceinline__ void gemm_body(
    int bm, int bn, const __half* __restrict__ A,
    const __half* __restrict__ Bt, int K,
    const float* __restrict__ bias, const float* __restrict__ resid,
    void* __restrict__ outv, int N, int flags)
{
    extern __shared__ uint32_t smu[];
    const int tid  = threadIdx.x;
    const int lane = tid & 31;
    const int warp = tid >> 5;
    const int wmi  = warp >> 2;
    const int wni  = warp & 3;
    const int lr   = lane >> 2;
    const int lc   = lane & 3;

    const int srow = tid >> 1;
    const int c0s  = (tid & 1) * 4;
    const unsigned sbase = (unsigned)__cvta_generic_to_shared(smu);
    unsigned adst[4], bdst[4];
    #pragma unroll
    for (int i = 0; i < 4; i++) {
        int c = c0s + i;
        unsigned off = (unsigned)(srow*128 + ((c ^ (srow & 7)) * 16));
        adst[i] = sbase + off;
        bdst[i] = sbase + 16384u + off;
    }
    const __half* aSrc = A  + (size_t)(bm + srow) * K + 8*c0s;
    const __half* bSrc = Bt + (size_t)(bn + srow) * K + 8*c0s;

    const int mi  = lane >> 3;
    const int mi0 = mi & 1, mi1 = mi >> 1;
    const int rw  = lane & 7;
    unsigned abase[4], bbase[2], aoff[4], boff[4];
    #pragma unroll
    for (int fm = 0; fm < 4; fm++)
        abase[fm] = sbase + (unsigned)((wmi*64 + fm*16 + mi0*8 + rw) * 128);
    #pragma unroll
    for (int g = 0; g < 2; g++)
        bbase[g] = sbase + 16384u + (unsigned)((wni*32 + (2*g + mi1)*8 + rw) * 128);
    #pragma unroll
    for (int t16 = 0; t16 < 4; t16++) {
        aoff[t16] = (unsigned)((((t16 << 1) | mi1) ^ rw) * 16);
        boff[t16] = (unsigned)((((t16 << 1) | mi0) ^ rw) * 16);
    }

    float acc[4][4][4];
    #pragma unroll
    for (int i = 0; i < 4; i++)
        #pragma unroll
        for (int j = 0; j < 4; j++)
            #pragma unroll
            for (int k = 0; k < 4; k++) acc[i][j][k] = 0.f;

    const int T = K >> 6;

    #define STAGE(t) do {                                                        \
        const unsigned boff_ = ((t) % 3) * 32768u;                               \
        const __half* sa = aSrc + (t) * 64;                                      \
        const __half* sb = bSrc + (t) * 64;                                      \
        _Pragma("unroll")                                                        \
        for (int i = 0; i < 4; i++) {                                            \
            cp16(adst[i] + boff_, sa + 8*i);                                     \
            cp16(bdst[i] + boff_, sb + 8*i);                                     \
        }                                                                        \
        cpcommit();                                                              \
    } while (0)

    STAGE(0); STAGE(1);

    for (int t = 0; t < T; t++) {
        if (t + 1 < T) cpwait1(); else cpwait0();
        __syncthreads();
        if (t + 2 < T) STAGE(t + 2);

        const unsigned sb_ = (t % 3) * 32768u;

        #pragma unroll
        for (int t16 = 0; t16 < 4; t16++) {
            uint32_t af[4][4], bf[2][4];
            #pragma unroll
            for (int fm = 0; fm < 4; fm++) ldsm_x4(af[fm], abase[fm] + aoff[t16] + sb_);
            #pragma unroll
            for (int g = 0; g < 2; g++)  ldsm_x4(bf[g],  bbase[g] + boff[t16] + sb_);
            #pragma unroll
            for (int fm = 0; fm < 4; fm++)
                #pragma unroll
                for (int fn = 0; fn < 4; fn++)
                    MMA_F16(acc[fm][fn], af[fm][0], af[fm][1], af[fm][2], af[fm][3],
                            bf[fn >> 1][(fn & 1) * 2], bf[fn >> 1][(fn & 1) * 2 + 1]);
        }
    }
    #undef STAGE

    const int do_gelu  = flags & 1;
    const int half_out = flags & 2;
    #pragma unroll
    for (int fm = 0; fm < 4; fm++) {
        #pragma unroll
        for (int fn = 0; fn < 4; fn++) {
            int row = bm + wmi*64 + fm*16 + lr;
            int col = bn + wni*32 + fn*8 + 2*lc;
            float2 bv = *(const float2*)(bias + col);

            float v0 = acc[fm][fn][0] + bv.x;
            float v1 = acc[fm][fn][1] + bv.y;
            float v2 = acc[fm][fn][2] + bv.x;
            float v3 = acc[fm][fn][3] + bv.y;
            if (do_gelu) {
                v0 = 0.5f * v0 * (1.f + erff(v0 * 0.70710678118654752f));
                v1 = 0.5f * v1 * (1.f + erff(v1 * 0.70710678118654752f));
                v2 = 0.5f * v2 * (1.f + erff(v2 * 0.70710678118654752f));
                v3 = 0.5f * v3 * (1.f + erff(v3 * 0.70710678118654752f));
            }
            if (resid) {
                float2 r0 = *(const float2*)(resid + (size_t)row * N + col);
                float2 r1 = *(const float2*)(resid + (size_t)(row + 8) * N + col);
                v0 += r0.x; v1 += r0.y; v2 += r1.x; v3 += r1.y;
            }
            if (half_out) {
                __half* o = (__half*)outv;
                *(__half2*)(o + (size_t)row * N + col)       = __floats2half2_rn(v0, v1);
                *(__half2*)(o + (size_t)(row + 8) * N + col) = __floats2half2_rn(v2, v3);
            } else {
                float* o = (float*)outv;
                *(float2*)(o + (size_t)row * N + col)        = make_float2(v0, v1);
                *(float2*)(o + (size_t)(row + 8) * N + col)  = make_float2(v2, v3);
            }
        }
    }
}

__global__ __launch_bounds__(256, 2) void gemm_f16(
    const __half* __restrict__ A, const __half* __restrict__ Bt,
    const float* __restrict__ bias, const float* __restrict__ resid,
    void* __restrict__ outv, int N, int K, int flags)
{
    gemm_body(blockIdx.y * 128, blockIdx.x * 128, A, Bt, K, bias, resid, outv, N, flags);
}

struct GProb { const __half* A; const __half* Bt; const float* bias;
               const float* resid; void* out; int N; int K; int gx; int flags; };
__global__ __launch_bounds__(256, 2) void gemm_f16_dual(GProb p0, GProb p1, int nblk0)
{
    int b = blockIdx.x;
    if (b < nblk0) {
        gemm_body((b / p0.gx) * 128, (b % p0.gx) * 128, p0.A, p0.Bt, p0.K,
                  p0.bias, p0.resid, p0.out, p0.N, p0.flags);
    } else {
        b -= nblk0;
        gemm_body((b / p1.gx) * 128, (b % p1.gx) * 128, p1.A, p1.Bt, p1.K,
                  p1.bias, p1.resid, p1.out, p1.N, p1.flags);
    }
}

// ---------------- LayerNorm ----------------
__global__ __launch_bounds__(256) void ln_kernel(
    const float* __restrict__ x, const float* __restrict__ g,
    const float* __restrict__ b, void* __restrict__ yv, int half_out)
{
    __shared__ float red[256];
    const int row = blockIdx.x;
    const int tid = threadIdx.x;
    const float* xr = x + (size_t)row * CC;

    float v[4];
    float s = 0.f;
    #pragma unroll
    for (int i = 0; i < 4; i++) { v[i] = xr[tid + i*256]; s += v[i]; }
    red[tid] = s; __syncthreads();
    for (int off = 128; off > 0; off >>= 1) {
        if (tid < off) red[tid] += red[tid + off];
        __syncthreads();
    }
    const float mean = red[0] * (1.f / CC);
    __syncthreads();

    float sq = 0.f;
    #pragma unroll
    for (int i = 0; i < 4; i++) { float d = v[i] - mean; sq += d * d; }
    red[tid] = sq; __syncthreads();
    for (int off = 128; off > 0; off >>= 1) {
        if (tid < off) red[tid] += red[tid + off];
        __syncthreads();
    }
    const float rstd = rsqrtf(red[0] * (1.f / CC) + EPSLN);

    #pragma unroll
    for (int i = 0; i < 4; i++) {
        int c = tid + i*256;
        float o = (v[i] - mean) * rstd * g[c] + b[c];
        if (half_out) ((__half*)yv)[(size_t)row * CC + c] = __float2half(o);
        else          ((float*)yv)[(size_t)row * CC + c] = o;
    }
}

// ---------------- fp16 flash attention v2 (R15, verified) ----------------
#define ASRH 36
#define AK_U32(b) (4608u + (b)*2304u)
#define AV_U32(b) (9216u + (b)*2304u)
#define AM_U32(b) (13824u + (b)*64u)
#define ATT_SMEM  (13952 * 4)

__global__ __launch_bounds__(256) void attn_f16(
    const __half* __restrict__ QH, const __half* __restrict__ KV,
    const int* __restrict__ mask, __half* __restrict__ OUT)
{
    extern __shared__ uint32_t sm32[];
    uint32_t* Qs = sm32;

    const int tid  = threadIdx.x;
    const int lane = tid & 31;
    const int warp = tid >> 5;
    const int lr   = lane >> 2;
    const int lc   = lane & 3;
    const int b = blockIdx.z, h = blockIdx.y;
    const int q0 = blockIdx.x * 128;

    const unsigned smbase = (unsigned)__cvta_generic_to_shared(sm32);

    const int srow = tid >> 2;
    const int sc0  = (tid & 3) * 2;
    const unsigned kst0 = smbase + (unsigned)(srow*144 + sc0*16);
    const __half* kvRow = KV + (size_t)(b*NC + srow) * (2*CC) + h*HD + sc0*8;
    const int* mrow = mask + b*NC + 4*tid;

    #define ASTAGE(c) do {                                                       \
        const int buf_ = (c) & 1;                                                \
        const __half* sk = kvRow + (size_t)(c) * 64 * (2*CC);                    \
        cp16(kst0 + AK_U32(buf_)*4u,      sk);                                   \
        cp16(kst0 + AK_U32(buf_)*4u + 16, sk + 8);                               \
        cp16(kst0 + AV_U32(buf_)*4u,      sk + CC);                              \
        cp16(kst0 + AV_U32(buf_)*4u + 16, sk + CC + 8);                          \
        if (tid < 16)                                                            \
            cp16(smbase + AM_U32(buf_)*4u + tid*16u, mrow + (c)*64);             \
        cpcommit();                                                              \
    } while (0)

    const int mi  = lane >> 3;
    const int mi0 = mi & 1, mi1 = mi >> 1;
    const int rw  = lane & 7;
    const unsigned qad = smbase + (unsigned)((16*warp + mi0*8 + rw)*144 + mi1*16);
    unsigned kad[4], vad[4];
    #pragma unroll
    for (int g = 0; g < 4; g++) {
        kad[g] = smbase + (unsigned)((16*g + mi1*8 + rw)*144 + mi0*16);
        vad[g] = smbase + (unsigned)((mi0*8 + rw)*144 + (16*g + mi1*8)*2);
    }

    {
        const __half2 sc = __float2half2_rn(0.125f);
        int r  = tid >> 1;
        int j0 = (tid & 1) * 8;
        const uint2* src = (const uint2*)(QH + (size_t)(b*NQ + q0 + r)*CC + h*HD);
        #pragma unroll
        for (int i = 0; i < 8; i++) {
            int j = j0 + i;
            uint2 v = src[j];
            __half2 h0 = __hmul2(*(__half2*)&v.x, sc);
            __half2 h1 = __hmul2(*(__half2*)&v.y, sc);
            Qs[r*ASRH + 2*j]     = *(uint32_t*)&h0;
            Qs[r*ASRH + 2*j + 1] = *(uint32_t*)&h1;
        }
    }
    ASTAGE(0);
    __syncthreads();

    uint32_t qf[4][4];
    #pragma unroll
    for (int t = 0; t < 4; t++) ldsm_x4(qf[t], qad + t*32u);

    const int row0 = 16*warp + lr;
    const int row1 = row0 + 8;

    float m0 = -1e30f, m1 = -1e30f, l0 = 0.f, l1 = 0.f;
    float oacc[8][4];
    #pragma unroll
    for (int fn = 0; fn < 8; fn++)
        #pragma unroll
        for (int r = 0; r < 4; r++) oacc[fn][r] = 0.f;

    const int NCC = NC / 64;
    for (int c = 0; c < NCC; c++) {
        cpwait0();
        __syncthreads();
        if (c + 1 < NCC) ASTAGE(c + 1);

        const unsigned kb = AK_U32(c & 1) * 4u;
        const unsigned vb = AV_U32(c & 1) * 4u;
        const int* mv = (const int*)(sm32 + AM_U32(c & 1));

        float sfr[8][4];
        #pragma unroll
        for (int fn = 0; fn < 8; fn++)
            #pragma unroll
            for (int r = 0; r < 4; r++) sfr[fn][r] = 0.f;

        #pragma unroll
        for (int t = 0; t < 4; t++) {
            uint32_t kf[4][4];
            #pragma unroll
            for (int g = 0; g < 4; g++) ldsm_x4(kf[g], kad[g] + kb + t*32u);
            #pragma unroll
            for (int fn = 0; fn < 8; fn++)
                MMA_F16(sfr[fn], qf[t][0], qf[t][1], qf[t][2], qf[t][3],
                        kf[fn >> 1][(fn & 1) * 2], kf[fn >> 1][(fn & 1) * 2 + 1]);
        }

        float mx0 = -1e30f, mx1 = -1e30f;
        #pragma unroll
        for (int fn = 0; fn < 8; fn++) {
            int col = 8*fn + 2*lc;
            float a0 = mv[col]     ? 0.f : -1e30f;
            float a1 = mv[col + 1] ? 0.f : -1e30f;
            sfr[fn][0] += a0; sfr[fn][1] += a1;
            sfr[fn][2] += a0; sfr[fn][3] += a1;
            mx0 = fmaxf(mx0, fmaxf(sfr[fn][0], sfr[fn][1]));
            mx1 = fmaxf(mx1, fmaxf(sfr[fn][2], sfr[fn][3]));
        }
        mx0 = fmaxf(mx0, __shfl_xor_sync(0xffffffffu, mx0, 1));
        mx0 = fmaxf(mx0, __shfl_xor_sync(0xffffffffu, mx0, 2));
        mx1 = fmaxf(mx1, __shfl_xor_sync(0xffffffffu, mx1, 1));
        mx1 = fmaxf(mx1, __shfl_xor_sync(0xffffffffu, mx1, 2));

        const float nm0 = fmaxf(m0, mx0);
        const float nm1 = fmaxf(m1, mx1);
        const float al0 = __expf(m0 - nm0);
        const float al1 = __expf(m1 - nm1);

        float sum0 = 0.f, sum1 = 0.f;
        uint32_t pf[4][4];
        #pragma unroll
        for (int t = 0; t < 4; t++) {
            const int fa = 2*t, fb = 2*t + 1;
            float p0 = __expf(sfr[fa][0] - nm0), p1 = __expf(sfr[fa][1] - nm0);
            float p2 = __expf(sfr[fa][2] - nm1), p3 = __expf(sfr[fa][3] - nm1);
            float p4 = __expf(sfr[fb][0] - nm0), p5 = __expf(sfr[fb][1] - nm0);
            float p6 = __expf(sfr[fb][2] - nm1), p7 = __expf(sfr[fb][3] - nm1);
            sum0 += p0 + p1 + p4 + p5;
            sum1 += p2 + p3 + p6 + p7;
            __half2 h0 = __floats2half2_rn(p0, p1);
            __half2 h1 = __floats2half2_rn(p2, p3);
            __half2 h2 = __floats2half2_rn(p4, p5);
            __half2 h3 = __floats2half2_rn(p6, p7);
            pf[t][0] = *(uint32_t*)&h0;
            pf[t][1] = *(uint32_t*)&h1;
            pf[t][2] = *(uint32_t*)&h2;
            pf[t][3] = *(uint32_t*)&h3;
        }
        sum0 += __shfl_xor_sync(0xffffffffu, sum0, 1);
        sum0 += __shfl_xor_sync(0xffffffffu, sum0, 2);
        sum1 += __shfl_xor_sync(0xffffffffu, sum1, 1);
        sum1 += __shfl_xor_sync(0xffffffffu, sum1, 2);

        l0 = l0 * al0 + sum0;
        l1 = l1 * al1 + sum1;
        m0 = nm0; m1 = nm1;

        #pragma unroll
        for (int fn = 0; fn < 8; fn++) {
            oacc[fn][0] *= al0; oacc[fn][1] *= al0;
            oacc[fn][2] *= al1; oacc[fn][3] *= al1;
        }

        #pragma unroll
        for (int t = 0; t < 4; t++) {
            uint32_t vf[4][4];
            #pragma unroll
            for (int g = 0; g < 4; g++) ldsm_x4t(vf[g], vad[g] + vb + t*2304u);
            #pragma unroll
            for (int fn = 0; fn < 8; fn++)
                MMA_F16(oacc[fn], pf[t][0], pf[t][1], pf[t][2], pf[t][3],
                        vf[fn >> 1][(fn & 1) * 2], vf[fn >> 1][(fn & 1) * 2 + 1]);
        }
    }
    #undef ASTAGE

    const float il0 = 1.f / l0;
    const float il1 = 1.f / l1;
    #pragma unroll
    for (int fn = 0; fn < 8; fn++) {
        int col = h*HD + 8*fn + 2*lc;
        *(__half2*)(OUT + (size_t)(b*NQ + q0 + row0)*CC + col) =
            __floats2half2_rn(oacc[fn][0]*il0, oacc[fn][1]*il0);
        *(__half2*)(OUT + (size_t)(b*NQ + q0 + row1)*CC + col) =
            __floats2half2_rn(oacc[fn][2]*il1, oacc[fn][3]*il1);
    }
}

// ---------------- orchestration ----------------
extern "C" void kernel_launch(void* const* d_in, const int* in_sizes, int n_in,
                              void* d_out, int out_size)
{
    const float* query   = (const float*)d_in[0];
    const float* context = (const float*)d_in[1];
    const int*   cmask   = (const int*)  d_in[2];
    const float* Wqp   = (const float*)d_in[3];
    const float* bqp   = (const float*)d_in[4];
    const float* Wcp   = (const float*)d_in[5];
    const float* bcp   = (const float*)d_in[6];
    const float* Wq    = (const float*)d_in[7];
    const float* bq    = (const float*)d_in[8];
    const float* Wkv   = (const float*)d_in[9];
    const float* bkv   = (const float*)d_in[10];
    const float* Wo    = (const float*)d_in[11];
    const float* bo    = (const float*)d_in[12];
    const float* g1    = (const float*)d_in[13];
    const float* beta1 = (const float*)d_in[14];
    const float* W1    = (const float*)d_in[15];
    const float* bf1   = (const float*)d_in[16];
    const float* W2    = (const float*)d_in[17];
    const float* bf2   = (const float*)d_in[18];
    const float* g2    = (const float*)d_in[19];
    const float* beta2 = (const float*)d_in[20];
    const float* gf    = (const float*)d_in[21];
    const float* betaf = (const float*)d_in[22];
    float* out = (float*)d_out;

    float  *bufQ;
    __half *bufC, *bufQN, *bufQH, *bufKV, *bufKV2, *bufO, *bufF;
    __half *rQuery, *rCtx, *rWqp, *rWcp, *rWq, *rWkv, *rWo, *rW1, *rW2;
    cudaGetSymbolAddress((void**)&bufQ,   g_bufQ);
    cudaGetSymbolAddress((void**)&bufC,   g_bufC);
    cudaGetSymbolAddress((void**)&bufQN,  g_bufQN);
    cudaGetSymbolAddress((void**)&bufQH,  g_bufQH);
    cudaGetSymbolAddress((void**)&bufKV,  g_bufKV);
    cudaGetSymbolAddress((void**)&bufKV2, g_bufKV2);
    cudaGetSymbolAddress((void**)&bufO,   g_bufO);
    cudaGetSymbolAddress((void**)&bufF,   g_bufF);
    cudaGetSymbolAddress((void**)&rQuery, g_rQuery);
    cudaGetSymbolAddress((void**)&rCtx,   g_rCtx);
    cudaGetSymbolAddress((void**)&rWqp,   g_rWqp);
    cudaGetSymbolAddress((void**)&rWcp,   g_rWcp);
    cudaGetSymbolAddress((void**)&rWq,    g_rWq);
    cudaGetSymbolAddress((void**)&rWkv,   g_rWkv);
    cudaGetSymbolAddress((void**)&rWo,    g_rWo);
    cudaGetSymbolAddress((void**)&rW1,    g_rW1);
    cudaGetSymbolAddress((void**)&rW2,    g_rW2);

    const int smem_gemm = 3 * 32768;   // 96 KB
    cudaFuncSetAttribute(gemm_f16,      cudaFuncAttributeMaxDynamicSharedMemorySize, smem_gemm);
    cudaFuncSetAttribute(gemm_f16_dual, cudaFuncAttributeMaxDynamicSharedMemorySize, smem_gemm);
    cudaFuncSetAttribute(attn_f16, cudaFuncAttributeMaxDynamicSharedMemorySize, ATT_SMEM);

    const dim3 blk(256);
    const int MQ = B_ * NQ;   // 2048
    const int MC = B_ * NC;   // 8192

    // fork-join stream + events (created fresh per call; capture-safe, not destroyed)
    cudaStream_t s2;
    cudaStreamCreateWithFlags(&s2, cudaStreamNonBlocking);
    cudaEvent_t evC, evK0, evK1;
    cudaEventCreateWithFlags(&evC,  cudaEventDisableTiming);
    cudaEventCreateWithFlags(&evK0, cudaEventDisableTiming);
    cudaEventCreateWithFlags(&evK1, cudaEventDisableTiming);

    // ---- prep (main stream) ----
    tohalf<<<(B_*NQ*DQ)/1024, 256>>>(query,   rQuery, B_*NQ*DQ);
    tohalf<<<(B_*NC*DC)/1024, 256>>>(context, rCtx,   B_*NC*DC);
    {
        TTtab tab; int off = 0, i = 0;
        auto add = [&](const float* s, __half* d, int K, int N) {
            tab.p[i] = TTp{s, d, K, N, off};
            off += (N/32) * (K/32); i++;
        };
        add(Wqp, rWqp, DQ, CC);
        add(Wcp, rWcp, DC, CC);
        for (int l = 0; l < LL; l++) {
            add(Wq  + (size_t)l*CC*CC,   rWq  + (size_t)l*CC*CC,   CC, CC);
            add(Wkv + (size_t)l*CC*2*CC, rWkv + (size_t)l*CC*2*CC, CC, 2*CC);
            add(Wo  + (size_t)l*CC*CC,   rWo  + (size_t)l*CC*CC,   CC, CC);
            add(W1  + (size_t)l*CC*FF,   rW1  + (size_t)l*CC*FF,   CC, FF);
        }
        transpose_mega<<<off, dim3(32, 8)>>>(tab);
    }
    {
        TTtab tab; int off = 0, i = 0;
        for (int l = 0; l < LL; l++) {
            tab.p[i] = TTp{W2 + (size_t)l*FF*CC, rW2 + (size_t)l*FF*CC, FF, CC, off};
            off += (CC/32) * (FF/32); i++;
        }
        for (; i < MAXTT; i++) tab.p[i] = tab.p[i-1];
        transpose_mega<<<off, dim3(32, 8)>>>(tab);
    }

    // ---- input projections: dual(Wcp big + Wqp small) ----
    {
        GProb pc { rCtx,   rWcp, bcp, nullptr, bufC, CC, DC, CC/128, 2 };
        GProb pq { rQuery, rWqp, bqp, nullptr, bufQ, CC, DQ, CC/128, 0 };
        int nblk0 = (CC/128) * (MC/128);   // 512
        int nblk1 = (CC/128) * (MQ/128);   // 128
        gemm_f16_dual<<<nblk0 + nblk1, blk, smem_gemm>>>(pc, pq, nblk0);
    }

    // fork: side stream computes BOTH layers' KV off bufC
    cudaEventRecord(evC, 0);
    cudaStreamWaitEvent(s2, evC, 0);
    gemm_f16<<<dim3(2*CC/128, MC/128), blk, smem_gemm, s2>>>(
        bufC, rWkv,                bkv,      nullptr, bufKV,  2*CC, CC, 2);
    cudaEventRecord(evK0, s2);
    gemm_f16<<<dim3(2*CC/128, MC/128), blk, smem_gemm, s2>>>(
        bufC, rWkv + (size_t)CC*2*CC, bkv + 2*CC, nullptr, bufKV2, 2*CC, CC, 2);
    cudaEventRecord(evK1, s2);

    __half* kvbuf[2] = { bufKV, bufKV2 };
    cudaEvent_t kvev[2] = { evK0, evK1 };

    for (int l = 0; l < LL; l++) {
        ln_kernel<<<MQ, 256>>>(bufQ, g1 + l*CC, beta1 + l*CC, bufQN, 1);
        gemm_f16<<<dim3(CC/128, MQ/128), blk, smem_gemm>>>(
            bufQN, rWq + (size_t)l*CC*CC, bq + l*CC, nullptr, bufQH, CC, CC, 2);

        cudaStreamWaitEvent(0, kvev[l], 0);   // join: KV for this layer ready
        attn_f16<<<dim3(NQ/128, HH, B_), blk, ATT_SMEM>>>(bufQH, kvbuf[l], cmask, bufO);

        gemm_f16<<<dim3(CC/128, MQ/128), blk, smem_gemm>>>(
            bufO, rWo + (size_t)l*CC*CC, bo + l*CC, bufQ, bufQ, CC, CC, 0);

        ln_kernel<<<MQ, 256>>>(bufQ, g2 + l*CC, beta2 + l*CC, bufQN, 1);

        gemm_f16<<<dim3(FF/128, MQ/128), blk, smem_gemm>>>(
            bufQN, rW1 + (size_t)l*CC*FF, bf1 + l*FF, nullptr, bufF, FF, CC, 3);
        gemm_f16<<<dim3(CC/128, MQ/128), blk, smem_gemm>>>(
            bufF, rW2 + (size_t)l*FF*CC, bf2 + l*CC, bufQ, bufQ, CC, FF, 0);
    }
    ln_kernel<<<MQ, 256>>>(bufQ, gf, betaf, out, 0);
}